// round 2
// baseline (speedup 1.0000x reference)
#include <cuda_runtime.h>
#include <math.h>

#define B_  4
#define T_  4096
#define C_  1024
#define H_  64
#define SCALE 0.03125f   // C^-0.5 = 1/32 exactly

// ---------------- scratch (device globals: no allocation allowed) ----------
__device__ float g_q[B_ * T_ * H_];
__device__ float g_k[B_ * T_ * H_];
__device__ float g_v[B_ * T_ * H_];

// ---------------------------------------------------------------------------
// Kernel 1: fused QKV projection.
// Grid: (B*T)/64 = 256 CTAs. Each CTA: 64 rows x 192 cols (Q|K|V), K tiled by 64.
// 256 threads, thread micro-tile 4 rows x 12 cols (cols strided by 16).
// smem: xs[64][65] + ws[64][192]  = 65,792 B (dynamic).
// ---------------------------------------------------------------------------
#define QKV_SMEM ((64 * 65 + 64 * 192) * 4)

__global__ void __launch_bounds__(256, 2)
qkv_kernel(const float* __restrict__ x,
           const float* __restrict__ Wq,
           const float* __restrict__ Wk,
           const float* __restrict__ Wv)
{
    extern __shared__ float sm[];
    float (*xs)[65]  = (float (*)[65])sm;
    float (*ws)[192] = (float (*)[192])(sm + 64 * 65);

    const int tid = threadIdx.x;
    const int tx  = tid & 15;      // 0..15
    const int ty  = tid >> 4;      // 0..15
    const int row0 = blockIdx.x * 64;

    float acc[4][12];
#pragma unroll
    for (int r = 0; r < 4; r++)
#pragma unroll
        for (int c = 0; c < 12; c++) acc[r][c] = 0.f;

    for (int k0 = 0; k0 < C_; k0 += 64) {
        // load x tile 64x64 (float4, coalesced)
#pragma unroll
        for (int i = 0; i < 4; i++) {
            int idx = tid + i * 256;          // 0..1023 float4 slots
            int r = idx >> 4;
            int c = (idx & 15) << 2;
            float4 v = *(const float4*)(x + (size_t)(row0 + r) * C_ + k0 + c);
            xs[r][c + 0] = v.x; xs[r][c + 1] = v.y;
            xs[r][c + 2] = v.z; xs[r][c + 3] = v.w;
        }
        // load W tiles: Wq|Wk|Wv rows k0..k0+63, all 64 cols each
#pragma unroll
        for (int i = 0; i < 4; i++) {
            int idx = tid + i * 256;
            int r = idx >> 4;
            int c = (idx & 15) << 2;
            size_t off = (size_t)(k0 + r) * H_ + c;
            *(float4*)&ws[r][c]       = *(const float4*)(Wq + off);
            *(float4*)&ws[r][64 + c]  = *(const float4*)(Wk + off);
            *(float4*)&ws[r][128 + c] = *(const float4*)(Wv + off);
        }
        __syncthreads();

#pragma unroll
        for (int kk = 0; kk < 64; kk++) {
            float a[4], b[12];
#pragma unroll
            for (int r = 0; r < 4; r++) a[r] = xs[ty * 4 + r][kk];
#pragma unroll
            for (int c = 0; c < 12; c++) b[c] = ws[kk][tx + 16 * c];
#pragma unroll
            for (int r = 0; r < 4; r++)
#pragma unroll
                for (int c = 0; c < 12; c++)
                    acc[r][c] = fmaf(a[r], b[c], acc[r][c]);
        }
        __syncthreads();
    }

    // store to scratch
#pragma unroll
    for (int r = 0; r < 4; r++) {
        int grow = row0 + ty * 4 + r;
#pragma unroll
        for (int c = 0; c < 12; c++) {
            int col = tx + 16 * c;
            float* dst = (col < 64) ? g_q : (col < 128 ? g_k : g_v);
            dst[(size_t)grow * H_ + (col & 63)] = acc[r][c];
        }
    }
}

// ---------------------------------------------------------------------------
// Kernel 2: causal flash attention.
// Grid: (T/64, B) = (64, 4). Heavy tiles first via reversed blockIdx.x.
// 256 threads: thread grid 16x16; S micro-tile 4x4 (cols strided by 16),
// output micro-tile 4 rows x 4 of 64 head dims (strided by 16).
// smem: Qs,Ks,Vs,Ps each [64][65] = 66,560 B (dynamic).
// ---------------------------------------------------------------------------
#define ATTN_SMEM (4 * 64 * 65 * 4)

__global__ void __launch_bounds__(256, 2)
attn_kernel(float* __restrict__ out)
{
    extern __shared__ float sm[];
    float (*Qs)[65] = (float (*)[65])sm;
    float (*Ks)[65] = (float (*)[65])(sm + 64 * 65);
    float (*Vs)[65] = (float (*)[65])(sm + 2 * 64 * 65);
    float (*Ps)[65] = (float (*)[65])(sm + 3 * 64 * 65);

    const int tid = threadIdx.x;
    const int tx  = tid & 15;
    const int ty  = tid >> 4;
    const int qi  = (gridDim.x - 1) - blockIdx.x;  // heavy (large qi) first
    const int b   = blockIdx.y;
    const int qbase = qi * 64;
    const float* qp = g_q + (size_t)b * T_ * H_;
    const float* kp = g_k + (size_t)b * T_ * H_;
    const float* vp = g_v + (size_t)b * T_ * H_;

    // load Q tile
#pragma unroll
    for (int i = 0; i < 4; i++) {
        int idx = tid + i * 256;
        int r = idx >> 4;
        int c = (idx & 15) << 2;
        float4 v = *(const float4*)(qp + (size_t)(qbase + r) * H_ + c);
        Qs[r][c + 0] = v.x; Qs[r][c + 1] = v.y;
        Qs[r][c + 2] = v.z; Qs[r][c + 3] = v.w;
    }

    float m[4], l[4], acc[4][4];
#pragma unroll
    for (int r = 0; r < 4; r++) {
        m[r] = -INFINITY; l[r] = 0.f;
#pragma unroll
        for (int c = 0; c < 4; c++) acc[r][c] = 0.f;
    }

    const int ntiles = qi + 1;
    for (int j = 0; j < ntiles; j++) {
        // load K, V tiles
#pragma unroll
        for (int i = 0; i < 4; i++) {
            int idx = tid + i * 256;
            int r = idx >> 4;
            int c = (idx & 15) << 2;
            size_t off = (size_t)(j * 64 + r) * H_ + c;
            float4 kv = *(const float4*)(kp + off);
            Ks[r][c + 0] = kv.x; Ks[r][c + 1] = kv.y;
            Ks[r][c + 2] = kv.z; Ks[r][c + 3] = kv.w;
            float4 vv = *(const float4*)(vp + off);
            Vs[r][c + 0] = vv.x; Vs[r][c + 1] = vv.y;
            Vs[r][c + 2] = vv.z; Vs[r][c + 3] = vv.w;
        }
        __syncthreads();

        // S = Q K^T * scale   (s[r][c]: row = ty*4+r, key = tx+16*c)
        float s[4][4];
#pragma unroll
        for (int r = 0; r < 4; r++)
#pragma unroll
            for (int c = 0; c < 4; c++) s[r][c] = 0.f;
#pragma unroll
        for (int kk = 0; kk < 64; kk++) {
            float a[4], bb[4];
#pragma unroll
            for (int r = 0; r < 4; r++) a[r] = Qs[ty * 4 + r][kk];
#pragma unroll
            for (int c = 0; c < 4; c++) bb[c] = Ks[tx + 16 * c][kk];
#pragma unroll
            for (int r = 0; r < 4; r++)
#pragma unroll
                for (int c = 0; c < 4; c++)
                    s[r][c] = fmaf(a[r], bb[c], s[r][c]);
        }

        // scale + causal mask (only diagonal tile needs masking)
        if (j == qi) {
#pragma unroll
            for (int r = 0; r < 4; r++) {
                int qrow = qbase + ty * 4 + r;
#pragma unroll
                for (int c = 0; c < 4; c++) {
                    int key = j * 64 + tx + 16 * c;
                    s[r][c] = (key > qrow) ? -INFINITY : s[r][c] * SCALE;
                }
            }
        } else {
#pragma unroll
            for (int r = 0; r < 4; r++)
#pragma unroll
                for (int c = 0; c < 4; c++) s[r][c] *= SCALE;
        }

        // online softmax: row max/sum reduced across the 16 tx lanes
        float mnew[4], alpha[4], lt[4];
#pragma unroll
        for (int r = 0; r < 4; r++) {
            float mt = s[r][0];
#pragma unroll
            for (int c = 1; c < 4; c++) mt = fmaxf(mt, s[r][c]);
#pragma unroll
            for (int off = 8; off; off >>= 1)
                mt = fmaxf(mt, __shfl_xor_sync(0xffffffffu, mt, off));
            mnew[r] = fmaxf(m[r], mt);
            float ls = 0.f;
#pragma unroll
            for (int c = 0; c < 4; c++) {
                s[r][c] = __expf(s[r][c] - mnew[r]);   // exp(-inf)=0 for masked
                ls += s[r][c];
            }
#pragma unroll
            for (int off = 8; off; off >>= 1)
                ls += __shfl_xor_sync(0xffffffffu, ls, off);
            lt[r] = ls;
            alpha[r] = __expf(m[r] - mnew[r]);
            l[r] = l[r] * alpha[r] + lt[r];
            m[r] = mnew[r];
        }

        // stage P
#pragma unroll
        for (int r = 0; r < 4; r++)
#pragma unroll
            for (int c = 0; c < 4; c++)
                Ps[ty * 4 + r][tx + 16 * c] = s[r][c];
        __syncthreads();

        // O = O*alpha + P V   (out col = tx+16*c)
#pragma unroll
        for (int r = 0; r < 4; r++)
#pragma unroll
            for (int c = 0; c < 4; c++) acc[r][c] *= alpha[r];
#pragma unroll
        for (int kk = 0; kk < 64; kk++) {
            float a[4], bb[4];
#pragma unroll
            for (int r = 0; r < 4; r++) a[r] = Ps[ty * 4 + r][kk];
#pragma unroll
            for (int c = 0; c < 4; c++) bb[c] = Vs[kk][tx + 16 * c];
#pragma unroll
            for (int r = 0; r < 4; r++)
#pragma unroll
                for (int c = 0; c < 4; c++)
                    acc[r][c] = fmaf(a[r], bb[c], acc[r][c]);
        }
        __syncthreads();   // before next tile overwrites Ks/Vs/Ps
    }

    // normalize + write
#pragma unroll
    for (int r = 0; r < 4; r++) {
        int qrow = qbase + ty * 4 + r;
        float inv = 1.f / l[r];
#pragma unroll
        for (int c = 0; c < 4; c++) {
            int h = tx + 16 * c;
            out[((size_t)b * T_ + qrow) * H_ + h] = acc[r][c] * inv;
        }
    }
}

// ---------------------------------------------------------------------------
extern "C" void kernel_launch(void* const* d_in, const int* in_sizes, int n_in,
                              void* d_out, int out_size)
{
    const float* x  = (const float*)d_in[0];
    const float* Wq = (const float*)d_in[1];
    const float* Wk = (const float*)d_in[2];
    const float* Wv = (const float*)d_in[3];
    float* out = (float*)d_out;

    cudaFuncSetAttribute(qkv_kernel,  cudaFuncAttributeMaxDynamicSharedMemorySize, QKV_SMEM);
    cudaFuncSetAttribute(attn_kernel, cudaFuncAttributeMaxDynamicSharedMemorySize, ATTN_SMEM);

    qkv_kernel<<<(B_ * T_) / 64, 256, QKV_SMEM>>>(x, Wq, Wk, Wv);
    attn_kernel<<<dim3(T_ / 64, B_), 256, ATTN_SMEM>>>(out);
}

// round 3
// speedup vs baseline: 1.7594x; 1.7594x over previous
#include <cuda_runtime.h>
#include <cuda_bf16.h>
#include <math.h>
#include <stdint.h>

#define B_ 4
#define T_ 4096
#define C_ 1024
#define H_ 64
#define SCALE 0.03125f

// scratch: split-bf16 Q (scaled), K, V^T
__device__ __nv_bfloat16 g_qh[B_*T_*H_], g_ql[B_*T_*H_];
__device__ __nv_bfloat16 g_kh[B_*T_*H_], g_kl[B_*T_*H_];
__device__ __nv_bfloat16 g_vh[B_*H_*T_], g_vl[B_*H_*T_];   // [b][h][t]

__device__ __forceinline__ uint32_t su32(const void* p){ return (uint32_t)__cvta_generic_to_shared(p); }
__device__ __forceinline__ void ldsm4(uint32_t a, uint32_t& r0, uint32_t& r1, uint32_t& r2, uint32_t& r3){
    asm volatile("ldmatrix.sync.aligned.m8n8.x4.shared.b16 {%0,%1,%2,%3}, [%4];"
                 : "=r"(r0),"=r"(r1),"=r"(r2),"=r"(r3) : "r"(a));
}
__device__ __forceinline__ void mma16816(float* d, const uint32_t* a, uint32_t b0, uint32_t b1){
    asm volatile("mma.sync.aligned.m16n8k16.row.col.f32.bf16.bf16.f32 "
                 "{%0,%1,%2,%3}, {%4,%5,%6,%7}, {%8,%9}, {%0,%1,%2,%3};"
                 : "+f"(d[0]),"+f"(d[1]),"+f"(d[2]),"+f"(d[3])
                 : "r"(a[0]),"r"(a[1]),"r"(a[2]),"r"(a[3]),"r"(b0),"r"(b1));
}
__device__ __forceinline__ void splitp(float x, float y, uint32_t& hi, uint32_t& lo){
    __nv_bfloat162 h = __float22bfloat162_rn(make_float2(x,y));
    float2 hf = __bfloat1622float2(h);
    __nv_bfloat162 l = __float22bfloat162_rn(make_float2(x-hf.x, y-hf.y));
    hi = *(uint32_t*)&h; lo = *(uint32_t*)&l;
}

// ---------------- Kernel 1: scalar QKV (proven), split-bf16 epilogue --------
#define QKV_SMEM ((64*65 + 64*192)*4)
__global__ void __launch_bounds__(256,2)
qkv_kernel(const float* __restrict__ x, const float* __restrict__ Wq,
           const float* __restrict__ Wk, const float* __restrict__ Wv)
{
    extern __shared__ float sm[];
    float (*xs)[65]  = (float (*)[65])sm;
    float (*ws)[192] = (float (*)[192])(sm + 64*65);
    const int tid = threadIdx.x, tx = tid & 15, ty = tid >> 4;
    const int row0 = blockIdx.x * 64;

    float acc[4][12];
#pragma unroll
    for (int r=0;r<4;r++)
#pragma unroll
        for (int c=0;c<12;c++) acc[r][c]=0.f;

    for (int k0=0;k0<C_;k0+=64){
#pragma unroll
        for (int i=0;i<4;i++){
            int idx=tid+i*256, r=idx>>4, c=(idx&15)<<2;
            float4 v=*(const float4*)(x+(size_t)(row0+r)*C_+k0+c);
            xs[r][c]=v.x; xs[r][c+1]=v.y; xs[r][c+2]=v.z; xs[r][c+3]=v.w;
        }
#pragma unroll
        for (int i=0;i<4;i++){
            int idx=tid+i*256, r=idx>>4, c=(idx&15)<<2;
            size_t off=(size_t)(k0+r)*H_+c;
            *(float4*)&ws[r][c]    =*(const float4*)(Wq+off);
            *(float4*)&ws[r][64+c] =*(const float4*)(Wk+off);
            *(float4*)&ws[r][128+c]=*(const float4*)(Wv+off);
        }
        __syncthreads();
#pragma unroll
        for (int kk=0;kk<64;kk++){
            float a[4],b[12];
#pragma unroll
            for (int r=0;r<4;r++) a[r]=xs[ty*4+r][kk];
#pragma unroll
            for (int c=0;c<12;c++) b[c]=ws[kk][tx+16*c];
#pragma unroll
            for (int r=0;r<4;r++)
#pragma unroll
                for (int c=0;c<12;c++) acc[r][c]=fmaf(a[r],b[c],acc[r][c]);
        }
        __syncthreads();
    }
#pragma unroll
    for (int r=0;r<4;r++){
        int grow=row0+ty*4+r;
#pragma unroll
        for (int c=0;c<12;c++){
            int col=tx+16*c, h=col&63;
            float v=acc[r][c];
            if (col<64) v*=SCALE;
            __nv_bfloat16 hb=__float2bfloat16(v);
            __nv_bfloat16 lb=__float2bfloat16(v-__bfloat162float(hb));
            if (col<64){ size_t o=(size_t)grow*H_+h; g_qh[o]=hb; g_ql[o]=lb; }
            else if (col<128){ size_t o=(size_t)grow*H_+h; g_kh[o]=hb; g_kl[o]=lb; }
            else { int b=grow>>12, t=grow&4095;
                   size_t o=((size_t)b*H_+h)*T_+t; g_vh[o]=hb; g_vl[o]=lb; }
        }
    }
}

// ---------------- Kernel 2: tensor-core flash attention ---------------------
// CTA = (qi,b): 64 queries, 128 thr = 4 warps x 16 rows. Key tiles of 64.
#define KS 72
__global__ void __launch_bounds__(128)
attn_kernel(float* __restrict__ out)
{
    __shared__ __nv_bfloat16 ksh[64*KS], ksl[64*KS], vsh[64*KS], vsl[64*KS];
    const int tid=threadIdx.x, lane=tid&31, w=tid>>5;
    const int qi=(int)gridDim.x-1-blockIdx.x, b=blockIdx.y;
    const int qr=qi*64 + w*16 + (lane>>2);          // this thread's row (and qr+8)

    const __nv_bfloat16 *qhp=g_qh+(size_t)b*T_*H_, *qlp=g_ql+(size_t)b*T_*H_;
    const __nv_bfloat16 *khp=g_kh+(size_t)b*T_*H_, *klp=g_kl+(size_t)b*T_*H_;
    const __nv_bfloat16 *vhp=g_vh+(size_t)b*H_*T_, *vlp=g_vl+(size_t)b*H_*T_;

    uint32_t qa_h[4][4], qa_l[4][4];
#pragma unroll
    for (int s=0;s<4;s++){
        int c0=s*16+(lane&3)*2;
        size_t r0=(size_t)qr*H_, r1=(size_t)(qr+8)*H_;
        qa_h[s][0]=*(const uint32_t*)(qhp+r0+c0);   qa_h[s][1]=*(const uint32_t*)(qhp+r1+c0);
        qa_h[s][2]=*(const uint32_t*)(qhp+r0+c0+8); qa_h[s][3]=*(const uint32_t*)(qhp+r1+c0+8);
        qa_l[s][0]=*(const uint32_t*)(qlp+r0+c0);   qa_l[s][1]=*(const uint32_t*)(qlp+r1+c0);
        qa_l[s][2]=*(const uint32_t*)(qlp+r0+c0+8); qa_l[s][3]=*(const uint32_t*)(qlp+r1+c0+8);
    }

    float o[8][4];
#pragma unroll
    for (int f=0;f<8;f++){ o[f][0]=0.f;o[f][1]=0.f;o[f][2]=0.f;o[f][3]=0.f; }
    float m0=-INFINITY,m1=-INFINITY,l0=0.f,l1=0.f;

    for (int j=0;j<=qi;j++){
        __syncthreads();
#pragma unroll
        for (int i=0;i<4;i++){
            int idx=tid+i*128, rr=idx>>3, c8=(idx&7)<<3;
            size_t sk=(size_t)(j*64+rr)*H_+c8;
            *(uint4*)&ksh[rr*KS+c8]=*(const uint4*)(khp+sk);
            *(uint4*)&ksl[rr*KS+c8]=*(const uint4*)(klp+sk);
            size_t sv=(size_t)rr*T_+j*64+c8;
            *(uint4*)&vsh[rr*KS+c8]=*(const uint4*)(vhp+sv);
            *(uint4*)&vsl[rr*KS+c8]=*(const uint4*)(vlp+sv);
        }
        __syncthreads();

        // S = Q K^T (scale folded into Q)
        float sa[8][4];
#pragma unroll
        for (int f=0;f<8;f++){ sa[f][0]=0.f;sa[f][1]=0.f;sa[f][2]=0.f;sa[f][3]=0.f; }
        int rb=(lane>>4)*8+(lane&7), cb=((lane>>3)&1)*8;
#pragma unroll
        for (int s=0;s<4;s++){
#pragma unroll
            for (int p=0;p<4;p++){
                uint32_t bh[4],bl[4];
                uint32_t ad=su32(ksh+(p*16+rb)*KS+s*16+cb);
                ldsm4(ad,bh[0],bh[1],bh[2],bh[3]);
                ad=su32(ksl+(p*16+rb)*KS+s*16+cb);
                ldsm4(ad,bl[0],bl[1],bl[2],bl[3]);
                mma16816(sa[p*2],  qa_h[s],bh[0],bh[1]);
                mma16816(sa[p*2],  qa_h[s],bl[0],bl[1]);
                mma16816(sa[p*2],  qa_l[s],bh[0],bh[1]);
                mma16816(sa[p*2+1],qa_h[s],bh[2],bh[3]);
                mma16816(sa[p*2+1],qa_h[s],bl[2],bl[3]);
                mma16816(sa[p*2+1],qa_l[s],bh[2],bh[3]);
            }
        }

        if (j==qi){
#pragma unroll
            for (int f=0;f<8;f++){
                int kg=j*64+f*8+(lane&3)*2;
                if (kg  >qr)   sa[f][0]=-INFINITY;
                if (kg+1>qr)   sa[f][1]=-INFINITY;
                if (kg  >qr+8) sa[f][2]=-INFINITY;
                if (kg+1>qr+8) sa[f][3]=-INFINITY;
            }
        }

        // online softmax: rows (qr) and (qr+8); reduce across lanes sharing lane>>2
        float mt0=-INFINITY,mt1=-INFINITY;
#pragma unroll
        for (int f=0;f<8;f++){
            mt0=fmaxf(mt0,fmaxf(sa[f][0],sa[f][1]));
            mt1=fmaxf(mt1,fmaxf(sa[f][2],sa[f][3]));
        }
        mt0=fmaxf(mt0,__shfl_xor_sync(~0u,mt0,1)); mt0=fmaxf(mt0,__shfl_xor_sync(~0u,mt0,2));
        mt1=fmaxf(mt1,__shfl_xor_sync(~0u,mt1,1)); mt1=fmaxf(mt1,__shfl_xor_sync(~0u,mt1,2));
        float mn0=fmaxf(m0,mt0), mn1=fmaxf(m1,mt1);
        float a0=__expf(m0-mn0), a1=__expf(m1-mn1);
        float s0=0.f,s1=0.f;
#pragma unroll
        for (int f=0;f<8;f++){
            sa[f][0]=__expf(sa[f][0]-mn0); s0+=sa[f][0];
            sa[f][1]=__expf(sa[f][1]-mn0); s0+=sa[f][1];
            sa[f][2]=__expf(sa[f][2]-mn1); s1+=sa[f][2];
            sa[f][3]=__expf(sa[f][3]-mn1); s1+=sa[f][3];
        }
        s0+=__shfl_xor_sync(~0u,s0,1); s0+=__shfl_xor_sync(~0u,s0,2);
        s1+=__shfl_xor_sync(~0u,s1,1); s1+=__shfl_xor_sync(~0u,s1,2);
        l0=l0*a0+s0; l1=l1*a1+s1; m0=mn0; m1=mn1;

        // P -> split-bf16 A fragments (k-step s over keys)
        uint32_t ph[4][4], pl[4][4];
#pragma unroll
        for (int s=0;s<4;s++){
            splitp(sa[2*s][0],  sa[2*s][1],  ph[s][0],pl[s][0]);
            splitp(sa[2*s][2],  sa[2*s][3],  ph[s][1],pl[s][1]);
            splitp(sa[2*s+1][0],sa[2*s+1][1],ph[s][2],pl[s][2]);
            splitp(sa[2*s+1][2],sa[2*s+1][3],ph[s][3],pl[s][3]);
        }
#pragma unroll
        for (int f=0;f<8;f++){ o[f][0]*=a0; o[f][1]*=a0; o[f][2]*=a1; o[f][3]*=a1; }

        // O += P V  (B = V^T fragments: n=h rows of vs, k=key cols)
#pragma unroll
        for (int s=0;s<4;s++){
#pragma unroll
            for (int p=0;p<4;p++){
                uint32_t bh[4],bl[4];
                uint32_t ad=su32(vsh+(p*16+rb)*KS+s*16+cb);
                ldsm4(ad,bh[0],bh[1],bh[2],bh[3]);
                ad=su32(vsl+(p*16+rb)*KS+s*16+cb);
                ldsm4(ad,bl[0],bl[1],bl[2],bl[3]);
                mma16816(o[p*2],  ph[s],bh[0],bh[1]);
                mma16816(o[p*2],  ph[s],bl[0],bl[1]);
                mma16816(o[p*2],  pl[s],bh[0],bh[1]);
                mma16816(o[p*2+1],ph[s],bh[2],bh[3]);
                mma16816(o[p*2+1],ph[s],bl[2],bl[3]);
                mma16816(o[p*2+1],pl[s],bh[2],bh[3]);
            }
        }
    }

    float i0=1.f/l0, i1=1.f/l1;
    size_t ob0=((size_t)b*T_+qr)*H_, ob1=((size_t)b*T_+qr+8)*H_;
#pragma unroll
    for (int f=0;f<8;f++){
        int h=f*8+(lane&3)*2;
        out[ob0+h]=o[f][0]*i0; out[ob0+h+1]=o[f][1]*i0;
        out[ob1+h]=o[f][2]*i1; out[ob1+h+1]=o[f][3]*i1;
    }
}

extern "C" void kernel_launch(void* const* d_in, const int* in_sizes, int n_in,
                              void* d_out, int out_size)
{
    const float* x =(const float*)d_in[0];
    const float* Wq=(const float*)d_in[1];
    const float* Wk=(const float*)d_in[2];
    const float* Wv=(const float*)d_in[3];
    cudaFuncSetAttribute(qkv_kernel, cudaFuncAttributeMaxDynamicSharedMemorySize, QKV_SMEM);
    qkv_kernel<<<(B_*T_)/64, 256, QKV_SMEM>>>(x, Wq, Wk, Wv);
    attn_kernel<<<dim3(T_/64, B_), 128>>>((float*)d_out);
}

// round 4
// speedup vs baseline: 3.1736x; 1.8038x over previous
#include <cuda_runtime.h>
#include <cuda_bf16.h>
#include <math.h>
#include <stdint.h>

#define B_ 4
#define T_ 4096
#define C_ 1024
#define H_ 64
#define IPB 288                       // segments per batch: sum(qi/8+1)
#define NIT (B_*IPB)

__device__ __nv_bfloat16 g_qh[B_*T_*H_], g_ql[B_*T_*H_];
__device__ __nv_bfloat16 g_kh[B_*T_*H_], g_kl[B_*T_*H_];
__device__ __nv_bfloat16 g_vh[B_*H_*T_], g_vl[B_*H_*T_];      // [b][h][t]
__device__ __nv_bfloat16 g_wh[192*C_],  g_wl[192*C_];          // W^T [n][k]
__device__ float g_pacc[(size_t)NIT*64*64];
__device__ float g_pm[NIT*64], g_pl[NIT*64];

__device__ __forceinline__ uint32_t su32(const void* p){ return (uint32_t)__cvta_generic_to_shared(p); }
__device__ __forceinline__ void ldsm4(uint32_t a, uint32_t& r0, uint32_t& r1, uint32_t& r2, uint32_t& r3){
    asm volatile("ldmatrix.sync.aligned.m8n8.x4.shared.b16 {%0,%1,%2,%3}, [%4];"
                 : "=r"(r0),"=r"(r1),"=r"(r2),"=r"(r3) : "r"(a));
}
__device__ __forceinline__ void mma16816(float* d, const uint32_t* a, uint32_t b0, uint32_t b1){
    asm volatile("mma.sync.aligned.m16n8k16.row.col.f32.bf16.bf16.f32 "
                 "{%0,%1,%2,%3}, {%4,%5,%6,%7}, {%8,%9}, {%0,%1,%2,%3};"
                 : "+f"(d[0]),"+f"(d[1]),"+f"(d[2]),"+f"(d[3])
                 : "r"(a[0]),"r"(a[1]),"r"(a[2]),"r"(a[3]),"r"(b0),"r"(b1));
}
__device__ __forceinline__ void splitp(float x, float y, uint32_t& hi, uint32_t& lo){
    __nv_bfloat162 h = __float22bfloat162_rn(make_float2(x,y));
    float2 hf = __bfloat1622float2(h);
    __nv_bfloat162 l = __float22bfloat162_rn(make_float2(x-hf.x, y-hf.y));
    hi = *(uint32_t*)&h; lo = *(uint32_t*)&l;
}

// ------------- Kernel 0: transpose+split weights; fold 1/32 into Wq ---------
__global__ void prep_w(const float* __restrict__ Wq, const float* __restrict__ Wk,
                       const float* __restrict__ Wv){
    int n = blockIdx.x;
    const float* src; int h; float sc = 1.0f;
    if (n < 64)       { src = Wq; h = n;       sc = 0.03125f; }
    else if (n < 128) { src = Wk; h = n - 64; }
    else              { src = Wv; h = n - 128; }
    for (int k = threadIdx.x; k < C_; k += blockDim.x){
        float v = src[(size_t)k*H_ + h] * sc;
        __nv_bfloat16 hb = __float2bfloat16(v);
        g_wh[(size_t)n*C_+k] = hb;
        g_wl[(size_t)n*C_+k] = __float2bfloat16(v - __bfloat162float(hb));
    }
}

// ------------- Kernel 1: tensor-core fused QKV ------------------------------
// 256 CTAs: 64 rows x 192 cols. 8 warps = 2m x 4n, warp tile 32x48. k-step 32.
#define XS 40
__global__ void __launch_bounds__(256)
qkv_kernel(const float* __restrict__ x){
    __shared__ __nv_bfloat16 xsh[64*XS], xsl[64*XS], wsh[192*XS], wsl[192*XS];
    const int tid=threadIdx.x, lane=tid&31, w=tid>>5;
    const int wm=w>>2, wn=w&3;
    const int row0=blockIdx.x*64;

    float acc[2][6][4];
#pragma unroll
    for(int a=0;a<2;a++)
#pragma unroll
        for(int b=0;b<6;b++)
#pragma unroll
            for(int i=0;i<4;i++) acc[a][b][i]=0.f;

    const int ra_ = (lane&15), ca_ = (lane>>4)*8;          // A ldsm addr parts
    const int rb_ = (lane>>4)*8+(lane&7), cb_=((lane>>3)&1)*8; // B ldsm addr parts

    for(int k0=0;k0<C_;k0+=32){
        __syncthreads();
#pragma unroll
        for(int i=0;i<2;i++){
            int idx=tid+i*256, r=idx>>3, c4=(idx&7)<<2;
            float4 v=*(const float4*)(x+(size_t)(row0+r)*C_+k0+c4);
            uint32_t h0,l0,h1,l1; splitp(v.x,v.y,h0,l0); splitp(v.z,v.w,h1,l1);
            *(uint2*)&xsh[r*XS+c4]=make_uint2(h0,h1);
            *(uint2*)&xsl[r*XS+c4]=make_uint2(l0,l1);
        }
#pragma unroll
        for(int i=0;i<3;i++){
            int idx=tid+i*256, r=idx>>2, c8=(idx&3)<<3;
            *(uint4*)&wsh[r*XS+c8]=*(const uint4*)(g_wh+(size_t)r*C_+k0+c8);
            *(uint4*)&wsl[r*XS+c8]=*(const uint4*)(g_wl+(size_t)r*C_+k0+c8);
        }
        __syncthreads();
#pragma unroll
        for(int ks=0;ks<32;ks+=16){
            uint32_t ah[2][4], al[2][4];
#pragma unroll
            for(int mf=0;mf<2;mf++){
                int rr=wm*32+mf*16+ra_, cc=ks+ca_;
                ldsm4(su32(xsh+rr*XS+cc),ah[mf][0],ah[mf][1],ah[mf][2],ah[mf][3]);
                ldsm4(su32(xsl+rr*XS+cc),al[mf][0],al[mf][1],al[mf][2],al[mf][3]);
            }
#pragma unroll
            for(int p=0;p<3;p++){
                int rr=wn*48+p*16+rb_, cc=ks+cb_;
                uint32_t bh[4],bl[4];
                ldsm4(su32(wsh+rr*XS+cc),bh[0],bh[1],bh[2],bh[3]);
                ldsm4(su32(wsl+rr*XS+cc),bl[0],bl[1],bl[2],bl[3]);
#pragma unroll
                for(int mf=0;mf<2;mf++){
#pragma unroll
                    for(int q=0;q<2;q++){
                        float* d=acc[mf][p*2+q];
                        mma16816(d,ah[mf],bh[2*q],bh[2*q+1]);
                        mma16816(d,ah[mf],bl[2*q],bl[2*q+1]);
                        mma16816(d,al[mf],bh[2*q],bh[2*q+1]);
                    }
                }
            }
        }
    }
    // epilogue: split to bf16 hi/lo, scatter to Q,K (row-major) / V (transposed)
#pragma unroll
    for(int mf=0;mf<2;mf++){
        int r0=row0+wm*32+mf*16+(lane>>2), r1=r0+8;
#pragma unroll
        for(int nf=0;nf<6;nf++){
            int n=wn*48+nf*8+(lane&3)*2, mat=n>>6, h=n&63;
            float* d=acc[mf][nf];
            uint32_t h0,l0,h1,l1; splitp(d[0],d[1],h0,l0); splitp(d[2],d[3],h1,l1);
            if(mat<2){
                __nv_bfloat16 *dh = mat? g_kh:g_qh, *dl = mat? g_kl:g_ql;
                *(uint32_t*)(dh+(size_t)r0*H_+h)=h0; *(uint32_t*)(dl+(size_t)r0*H_+h)=l0;
                *(uint32_t*)(dh+(size_t)r1*H_+h)=h1; *(uint32_t*)(dl+(size_t)r1*H_+h)=l1;
            } else {
                int b0=r0>>12, t0=r0&4095, b1=r1>>12, t1=r1&4095;
                size_t o0=((size_t)b0*H_+h)*T_+t0, o1=((size_t)b1*H_+h)*T_+t1;
                __nv_bfloat162 H0=*(__nv_bfloat162*)&h0, L0=*(__nv_bfloat162*)&l0;
                __nv_bfloat162 H1=*(__nv_bfloat162*)&h1, L1=*(__nv_bfloat162*)&l1;
                g_vh[o0]=H0.x; g_vh[o0+T_]=H0.y; g_vl[o0]=L0.x; g_vl[o0+T_]=L0.y;
                g_vh[o1]=H1.x; g_vh[o1+T_]=H1.y; g_vl[o1]=L1.x; g_vl[o1+T_]=L1.y;
            }
        }
    }
}

// ------------- Kernel 2: split-key flash attention (partials) ---------------
// CTA = (b, qi, seg): 64 queries x <=8 key tiles. 128 thr = 4 warps x 16 rows.
#define KS 72
__global__ void __launch_bounds__(128)
attn_kernel(){
    __shared__ __nv_bfloat16 ksh[64*KS], ksl[64*KS], vsh[64*KS], vsl[64*KS];
    const int tid=threadIdx.x, lane=tid&31, w=tid>>5;
    int id=(int)gridDim.x-1-blockIdx.x;            // heavy first
    int b=id/IPB, r=id%IPB, qi=0;
    for(;;){ int c=(qi>>3)+1; if(r<c) break; r-=c; qi++; }
    const int j0=r*8, j1=min(j0+8, qi+1);
    const int qrl=w*16+(lane>>2);                   // local query row (and +8)
    const int qr=qi*64+qrl;

    const __nv_bfloat16 *qhp=g_qh+(size_t)b*T_*H_, *qlp=g_ql+(size_t)b*T_*H_;
    const __nv_bfloat16 *khp=g_kh+(size_t)b*T_*H_, *klp=g_kl+(size_t)b*T_*H_;
    const __nv_bfloat16 *vhp=g_vh+(size_t)b*H_*T_, *vlp=g_vl+(size_t)b*H_*T_;

    uint32_t qa_h[4][4], qa_l[4][4];
#pragma unroll
    for(int s=0;s<4;s++){
        int c0=s*16+(lane&3)*2;
        size_t o0=(size_t)qr*H_, o1=(size_t)(qr+8)*H_;
        qa_h[s][0]=*(const uint32_t*)(qhp+o0+c0);   qa_h[s][1]=*(const uint32_t*)(qhp+o1+c0);
        qa_h[s][2]=*(const uint32_t*)(qhp+o0+c0+8); qa_h[s][3]=*(const uint32_t*)(qhp+o1+c0+8);
        qa_l[s][0]=*(const uint32_t*)(qlp+o0+c0);   qa_l[s][1]=*(const uint32_t*)(qlp+o1+c0);
        qa_l[s][2]=*(const uint32_t*)(qlp+o0+c0+8); qa_l[s][3]=*(const uint32_t*)(qlp+o1+c0+8);
    }

    float o[8][4];
#pragma unroll
    for(int f=0;f<8;f++){o[f][0]=0.f;o[f][1]=0.f;o[f][2]=0.f;o[f][3]=0.f;}
    float m0=-INFINITY,m1=-INFINITY,l0=0.f,l1=0.f;
    const int rb=(lane>>4)*8+(lane&7), cb=((lane>>3)&1)*8;

    for(int j=j0;j<j1;j++){
        __syncthreads();
#pragma unroll
        for(int i=0;i<4;i++){
            int idx=tid+i*128, rr=idx>>3, c8=(idx&7)<<3;
            size_t sk=(size_t)(j*64+rr)*H_+c8;
            *(uint4*)&ksh[rr*KS+c8]=*(const uint4*)(khp+sk);
            *(uint4*)&ksl[rr*KS+c8]=*(const uint4*)(klp+sk);
            size_t sv=(size_t)rr*T_+j*64+c8;
            *(uint4*)&vsh[rr*KS+c8]=*(const uint4*)(vhp+sv);
            *(uint4*)&vsl[rr*KS+c8]=*(const uint4*)(vlp+sv);
        }
        __syncthreads();

        float sa[8][4];
#pragma unroll
        for(int f=0;f<8;f++){sa[f][0]=0.f;sa[f][1]=0.f;sa[f][2]=0.f;sa[f][3]=0.f;}
#pragma unroll
        for(int s=0;s<4;s++)
#pragma unroll
            for(int p=0;p<4;p++){
                uint32_t bh[4],bl[4];
                ldsm4(su32(ksh+(p*16+rb)*KS+s*16+cb),bh[0],bh[1],bh[2],bh[3]);
                ldsm4(su32(ksl+(p*16+rb)*KS+s*16+cb),bl[0],bl[1],bl[2],bl[3]);
                mma16816(sa[p*2],  qa_h[s],bh[0],bh[1]);
                mma16816(sa[p*2],  qa_h[s],bl[0],bl[1]);
                mma16816(sa[p*2],  qa_l[s],bh[0],bh[1]);
                mma16816(sa[p*2+1],qa_h[s],bh[2],bh[3]);
                mma16816(sa[p*2+1],qa_h[s],bl[2],bl[3]);
                mma16816(sa[p*2+1],qa_l[s],bh[2],bh[3]);
            }

        if(j==qi){
#pragma unroll
            for(int f=0;f<8;f++){
                int kg=j*64+f*8+(lane&3)*2;
                if(kg  >qr)   sa[f][0]=-INFINITY;
                if(kg+1>qr)   sa[f][1]=-INFINITY;
                if(kg  >qr+8) sa[f][2]=-INFINITY;
                if(kg+1>qr+8) sa[f][3]=-INFINITY;
            }
        }

        float mt0=-INFINITY,mt1=-INFINITY;
#pragma unroll
        for(int f=0;f<8;f++){
            mt0=fmaxf(mt0,fmaxf(sa[f][0],sa[f][1]));
            mt1=fmaxf(mt1,fmaxf(sa[f][2],sa[f][3]));
        }
        mt0=fmaxf(mt0,__shfl_xor_sync(~0u,mt0,1)); mt0=fmaxf(mt0,__shfl_xor_sync(~0u,mt0,2));
        mt1=fmaxf(mt1,__shfl_xor_sync(~0u,mt1,1)); mt1=fmaxf(mt1,__shfl_xor_sync(~0u,mt1,2));
        float mn0=fmaxf(m0,mt0), mn1=fmaxf(m1,mt1);
        float a0=__expf(m0-mn0), a1=__expf(m1-mn1);
        float s0=0.f,s1=0.f;
#pragma unroll
        for(int f=0;f<8;f++){
            sa[f][0]=__expf(sa[f][0]-mn0); s0+=sa[f][0];
            sa[f][1]=__expf(sa[f][1]-mn0); s0+=sa[f][1];
            sa[f][2]=__expf(sa[f][2]-mn1); s1+=sa[f][2];
            sa[f][3]=__expf(sa[f][3]-mn1); s1+=sa[f][3];
        }
        s0+=__shfl_xor_sync(~0u,s0,1); s0+=__shfl_xor_sync(~0u,s0,2);
        s1+=__shfl_xor_sync(~0u,s1,1); s1+=__shfl_xor_sync(~0u,s1,2);
        l0=l0*a0+s0; l1=l1*a1+s1; m0=mn0; m1=mn1;

        uint32_t ph[4][4], pl[4][4];
#pragma unroll
        for(int s=0;s<4;s++){
            splitp(sa[2*s][0],  sa[2*s][1],  ph[s][0],pl[s][0]);
            splitp(sa[2*s][2],  sa[2*s][3],  ph[s][1],pl[s][1]);
            splitp(sa[2*s+1][0],sa[2*s+1][1],ph[s][2],pl[s][2]);
            splitp(sa[2*s+1][2],sa[2*s+1][3],ph[s][3],pl[s][3]);
        }
#pragma unroll
        for(int f=0;f<8;f++){o[f][0]*=a0;o[f][1]*=a0;o[f][2]*=a1;o[f][3]*=a1;}
#pragma unroll
        for(int s=0;s<4;s++)
#pragma unroll
            for(int p=0;p<4;p++){
                uint32_t bh[4],bl[4];
                ldsm4(su32(vsh+(p*16+rb)*KS+s*16+cb),bh[0],bh[1],bh[2],bh[3]);
                ldsm4(su32(vsl+(p*16+rb)*KS+s*16+cb),bl[0],bl[1],bl[2],bl[3]);
                mma16816(o[p*2],  ph[s],bh[0],bh[1]);
                mma16816(o[p*2],  ph[s],bl[0],bl[1]);
                mma16816(o[p*2],  pl[s],bh[0],bh[1]);
                mma16816(o[p*2+1],ph[s],bh[2],bh[3]);
                mma16816(o[p*2+1],ph[s],bl[2],bl[3]);
                mma16816(o[p*2+1],pl[s],bh[2],bh[3]);
            }
    }

    // write partial (unnormalized O, m, l)
    float* pp=g_pacc+(size_t)id*4096;
#pragma unroll
    for(int f=0;f<8;f++){
        int h=f*8+(lane&3)*2;
        *(float2*)(pp+qrl*64+h)    =make_float2(o[f][0],o[f][1]);
        *(float2*)(pp+(qrl+8)*64+h)=make_float2(o[f][2],o[f][3]);
    }
    if((lane&3)==0){
        g_pm[id*64+qrl]=m0;   g_pl[id*64+qrl]=l0;
        g_pm[id*64+qrl+8]=m1; g_pl[id*64+qrl+8]=l1;
    }
}

// ------------- Kernel 3: combine split-key partials -------------------------
__global__ void __launch_bounds__(256)
comb_kernel(float* __restrict__ out){
    const int qi=blockIdx.x, b=blockIdx.y;
    const int a=qi>>3, rr=qi&7;
    const int base=b*IPB+(a+1)*(4*a+rr), nseg=a+1;
    const int ql=threadIdx.x>>2, hg=(threadIdx.x&3)*16;

    float mstar=-INFINITY;
    for(int s=0;s<nseg;s++) mstar=fmaxf(mstar,g_pm[(base+s)*64+ql]);
    float lsum=0.f, acc[16];
#pragma unroll
    for(int i=0;i<16;i++) acc[i]=0.f;
    for(int s=0;s<nseg;s++){
        float wgt=__expf(g_pm[(base+s)*64+ql]-mstar);
        lsum+=g_pl[(base+s)*64+ql]*wgt;
        const float4* p=(const float4*)(g_pacc+((size_t)(base+s)*4096+ql*64+hg));
#pragma unroll
        for(int i=0;i<4;i++){
            float4 v=p[i];
            acc[4*i]  +=wgt*v.x; acc[4*i+1]+=wgt*v.y;
            acc[4*i+2]+=wgt*v.z; acc[4*i+3]+=wgt*v.w;
        }
    }
    float inv=1.f/lsum;
    float4* po=(float4*)(out+((size_t)b*T_+qi*64+ql)*H_+hg);
#pragma unroll
    for(int i=0;i<4;i++)
        po[i]=make_float4(acc[4*i]*inv,acc[4*i+1]*inv,acc[4*i+2]*inv,acc[4*i+3]*inv);
}

extern "C" void kernel_launch(void* const* d_in, const int* in_sizes, int n_in,
                              void* d_out, int out_size){
    const float* x =(const float*)d_in[0];
    prep_w<<<192,256>>>((const float*)d_in[1],(const float*)d_in[2],(const float*)d_in[3]);
    qkv_kernel<<<(B_*T_)/64,256>>>(x);
    attn_kernel<<<NIT,128>>>();
    comb_kernel<<<dim3(T_/64,B_),256>>>((float*)d_out);
}

// round 5
// speedup vs baseline: 3.5133x; 1.1070x over previous
#include <cuda_runtime.h>
#include <cuda_bf16.h>
#include <math.h>
#include <stdint.h>

#define B_ 4
#define T_ 4096
#define C_ 1024
#define H_ 64
#define IPB 288
#define NIT (B_*IPB)

__device__ __nv_bfloat16 g_qh[B_*T_*H_], g_ql[B_*T_*H_];
__device__ __nv_bfloat16 g_kh[B_*T_*H_], g_kl[B_*T_*H_];
__device__ __nv_bfloat16 g_vh[B_*H_*T_], g_vl[B_*H_*T_];   // [b][h][t]
__device__ __nv_bfloat16 g_wh[192*C_],  g_wl[192*C_];       // W^T [n][k]
__device__ float g_pacc[(size_t)NIT*64*64];
__device__ float g_pm[NIT*64], g_pl[NIT*64];

__device__ __forceinline__ uint32_t su32(const void* p){ return (uint32_t)__cvta_generic_to_shared(p); }
__device__ __forceinline__ void ldsm4(uint32_t a, uint32_t& r0, uint32_t& r1, uint32_t& r2, uint32_t& r3){
    asm volatile("ldmatrix.sync.aligned.m8n8.x4.shared.b16 {%0,%1,%2,%3}, [%4];"
                 : "=r"(r0),"=r"(r1),"=r"(r2),"=r"(r3) : "r"(a));
}
__device__ __forceinline__ void mma16816(float* d, const uint32_t* a, uint32_t b0, uint32_t b1){
    asm volatile("mma.sync.aligned.m16n8k16.row.col.f32.bf16.bf16.f32 "
                 "{%0,%1,%2,%3}, {%4,%5,%6,%7}, {%8,%9}, {%0,%1,%2,%3};"
                 : "+f"(d[0]),"+f"(d[1]),"+f"(d[2]),"+f"(d[3])
                 : "r"(a[0]),"r"(a[1]),"r"(a[2]),"r"(a[3]),"r"(b0),"r"(b1));
}
__device__ __forceinline__ void splitp(float x, float y, uint32_t& hi, uint32_t& lo){
    __nv_bfloat162 h = __float22bfloat162_rn(make_float2(x,y));
    float2 hf = __bfloat1622float2(h);
    __nv_bfloat162 l = __float22bfloat162_rn(make_float2(x-hf.x, y-hf.y));
    hi = *(uint32_t*)&h; lo = *(uint32_t*)&l;
}
__device__ __forceinline__ void cpa16(uint32_t dst, const void* src){
    asm volatile("cp.async.cg.shared.global [%0], [%1], 16;"::"r"(dst),"l"(src));
}
__device__ __forceinline__ void cpcommit(){ asm volatile("cp.async.commit_group;"); }
template<int N> __device__ __forceinline__ void cpwait(){
    asm volatile("cp.async.wait_group %0;"::"n"(N));
}

// ------------- Kernel 0: transpose+split weights (coalesced), fold 1/32 -----
__global__ void __launch_bounds__(256)
prep_w(const float* __restrict__ Wq, const float* __restrict__ Wk,
       const float* __restrict__ Wv){
    __shared__ float t[64][65];
    const int tid=threadIdx.x, k0=blockIdx.x*64, mat=blockIdx.y;
    const float* src = mat==0?Wq:(mat==1?Wk:Wv);
    const float sc = mat==0?0.03125f:1.f;
#pragma unroll
    for(int i=0;i<4;i++){
        int idx=tid+i*256, r=idx>>4, c=(idx&15)<<2;
        float4 v=*(const float4*)(src+(size_t)(k0+r)*H_+c);
        t[r][c]=v.x*sc; t[r][c+1]=v.y*sc; t[r][c+2]=v.z*sc; t[r][c+3]=v.w*sc;
    }
    __syncthreads();
    const int h=tid>>2, kk=(tid&3)<<4, n=mat*64+h;
#pragma unroll
    for(int m=0;m<16;m++){
        float v=t[kk+m][h];
        __nv_bfloat16 hb=__float2bfloat16(v);
        g_wh[(size_t)n*C_+k0+kk+m]=hb;
        g_wl[(size_t)n*C_+k0+kk+m]=__float2bfloat16(v-__bfloat162float(hb));
    }
}

// ------------- Kernel 1: tensor-core fused QKV, double-buffered -------------
#define XS 40
#define XTS (64*XS)
#define WTS (192*XS)
#define QKV_SMEM ((4*XTS+4*WTS)*2)
__global__ void __launch_bounds__(256)
qkv_kernel(const float* __restrict__ x){
    extern __shared__ __nv_bfloat16 sm[];
    __nv_bfloat16 *xsh=sm, *xsl=sm+2*XTS, *wsh=sm+4*XTS, *wsl=sm+4*XTS+2*WTS;
    const int tid=threadIdx.x, lane=tid&31, w=tid>>5;
    const int wm=w>>2, wn=w&3;
    const int row0=blockIdx.x*64;

    float acc[2][6][4];
#pragma unroll
    for(int a=0;a<2;a++)
#pragma unroll
        for(int b=0;b<6;b++)
#pragma unroll
            for(int i=0;i<4;i++) acc[a][b][i]=0.f;

    const int ra_=(lane&15), ca_=(lane>>4)*8;
    const int rb_=(lane>>4)*8+(lane&7), cb_=((lane>>3)&1)*8;
    const int xr0=tid>>3, xc0=(tid&7)<<2;          // x load: 2 float4/thread
    const int wr0=tid>>2, wc0=(tid&3)<<3;          // W load: 3 cp.async/array

    // prologue: x regs for k0=0, cp.async W stage0
    float4 xv[2];
    xv[0]=*(const float4*)(x+(size_t)(row0+xr0)*C_+xc0);
    xv[1]=*(const float4*)(x+(size_t)(row0+xr0+32)*C_+xc0);
#pragma unroll
    for(int i=0;i<3;i++){
        int r=wr0+i*64;
        cpa16(su32(wsh+r*XS+wc0), g_wh+(size_t)r*C_+wc0);
        cpa16(su32(wsl+r*XS+wc0), g_wl+(size_t)r*C_+wc0);
    }
    cpcommit();

    for(int k0=0, it=0; k0<C_; k0+=32, it++){
        const int cur=it&1;
        const bool more = (k0+32<C_);
        if(more){
#pragma unroll
            for(int i=0;i<3;i++){
                int r=wr0+i*64;
                cpa16(su32(wsh+(cur^1)*WTS+r*XS+wc0), g_wh+(size_t)r*C_+k0+32+wc0);
                cpa16(su32(wsl+(cur^1)*WTS+r*XS+wc0), g_wl+(size_t)r*C_+k0+32+wc0);
            }
            cpcommit();
        }
        // split + STS current x
#pragma unroll
        for(int i=0;i<2;i++){
            uint32_t h0,l0,h1,l1;
            splitp(xv[i].x,xv[i].y,h0,l0); splitp(xv[i].z,xv[i].w,h1,l1);
            int r=xr0+i*32;
            *(uint2*)&xsh[cur*XTS+r*XS+xc0]=make_uint2(h0,h1);
            *(uint2*)&xsl[cur*XTS+r*XS+xc0]=make_uint2(l0,l1);
        }
        // prefetch next x
        if(more){
            xv[0]=*(const float4*)(x+(size_t)(row0+xr0)*C_+k0+32+xc0);
            xv[1]=*(const float4*)(x+(size_t)(row0+xr0+32)*C_+k0+32+xc0);
        }
        if(more) cpwait<1>(); else cpwait<0>();
        __syncthreads();

#pragma unroll
        for(int ks=0;ks<32;ks+=16){
            uint32_t ah[2][4], al[2][4];
#pragma unroll
            for(int mf=0;mf<2;mf++){
                int rr=wm*32+mf*16+ra_, cc=ks+ca_;
                ldsm4(su32(xsh+cur*XTS+rr*XS+cc),ah[mf][0],ah[mf][1],ah[mf][2],ah[mf][3]);
                ldsm4(su32(xsl+cur*XTS+rr*XS+cc),al[mf][0],al[mf][1],al[mf][2],al[mf][3]);
            }
#pragma unroll
            for(int p=0;p<3;p++){
                int rr=wn*48+p*16+rb_, cc=ks+cb_;
                uint32_t bh[4],bl[4];
                ldsm4(su32(wsh+cur*WTS+rr*XS+cc),bh[0],bh[1],bh[2],bh[3]);
                ldsm4(su32(wsl+cur*WTS+rr*XS+cc),bl[0],bl[1],bl[2],bl[3]);
#pragma unroll
                for(int mf=0;mf<2;mf++)
#pragma unroll
                    for(int q=0;q<2;q++){
                        float* d=acc[mf][p*2+q];
                        mma16816(d,ah[mf],bh[2*q],bh[2*q+1]);
                        mma16816(d,ah[mf],bl[2*q],bl[2*q+1]);
                        mma16816(d,al[mf],bh[2*q],bh[2*q+1]);
                    }
            }
        }
        __syncthreads();
    }
#pragma unroll
    for(int mf=0;mf<2;mf++){
        int r0=row0+wm*32+mf*16+(lane>>2), r1=r0+8;
#pragma unroll
        for(int nf=0;nf<6;nf++){
            int n=wn*48+nf*8+(lane&3)*2, mat=n>>6, h=n&63;
            float* d=acc[mf][nf];
            uint32_t h0,l0,h1,l1; splitp(d[0],d[1],h0,l0); splitp(d[2],d[3],h1,l1);
            if(mat<2){
                __nv_bfloat16 *dh=mat?g_kh:g_qh, *dl=mat?g_kl:g_ql;
                *(uint32_t*)(dh+(size_t)r0*H_+h)=h0; *(uint32_t*)(dl+(size_t)r0*H_+h)=l0;
                *(uint32_t*)(dh+(size_t)r1*H_+h)=h1; *(uint32_t*)(dl+(size_t)r1*H_+h)=l1;
            } else {
                int b0=r0>>12, t0=r0&4095, b1=r1>>12, t1=r1&4095;
                size_t o0=((size_t)b0*H_+h)*T_+t0, o1=((size_t)b1*H_+h)*T_+t1;
                __nv_bfloat162 H0=*(__nv_bfloat162*)&h0, L0=*(__nv_bfloat162*)&l0;
                __nv_bfloat162 H1=*(__nv_bfloat162*)&h1, L1=*(__nv_bfloat162*)&l1;
                g_vh[o0]=H0.x; g_vh[o0+T_]=H0.y; g_vl[o0]=L0.x; g_vl[o0+T_]=L0.y;
                g_vh[o1]=H1.x; g_vh[o1+T_]=H1.y; g_vl[o1]=L1.x; g_vl[o1+T_]=L1.y;
            }
        }
    }
}

// ------------- Kernel 2: split-key flash attention, double-buffered ---------
#define KS 72
#define STG (64*KS)
#define ATTN_SMEM (8*STG*2)
__global__ void __launch_bounds__(128)
attn_kernel(){
    extern __shared__ __nv_bfloat16 asm_[];
    __nv_bfloat16 *ksh=asm_, *ksl=asm_+2*STG, *vsh=asm_+4*STG, *vsl=asm_+6*STG;
    const int tid=threadIdx.x, lane=tid&31, w=tid>>5;
    int id=(int)gridDim.x-1-blockIdx.x;
    int b=id/IPB, r=id%IPB, qi=0;
    for(;;){ int c=(qi>>3)+1; if(r<c) break; r-=c; qi++; }
    const int j0=r*8, j1=min(j0+8, qi+1);
    const int qrl=w*16+(lane>>2), qr=qi*64+qrl;

    const __nv_bfloat16 *qhp=g_qh+(size_t)b*T_*H_, *qlp=g_ql+(size_t)b*T_*H_;
    const __nv_bfloat16 *khp=g_kh+(size_t)b*T_*H_, *klp=g_kl+(size_t)b*T_*H_;
    const __nv_bfloat16 *vhp=g_vh+(size_t)b*H_*T_, *vlp=g_vl+(size_t)b*H_*T_;
    const int lr=tid>>3, lc=(tid&7)<<3;   // load coords: 8 rows/thread-iter

    // prologue: stage 0 <- tile j0
#pragma unroll
    for(int i=0;i<4;i++){
        int rr=lr+i*16;
        cpa16(su32(ksh+rr*KS+lc), khp+(size_t)(j0*64+rr)*H_+lc);
        cpa16(su32(ksl+rr*KS+lc), klp+(size_t)(j0*64+rr)*H_+lc);
        cpa16(su32(vsh+rr*KS+lc), vhp+(size_t)rr*T_+j0*64+lc);
        cpa16(su32(vsl+rr*KS+lc), vlp+(size_t)rr*T_+j0*64+lc);
    }
    cpcommit();

    uint32_t qa_h[4][4], qa_l[4][4];
#pragma unroll
    for(int s=0;s<4;s++){
        int c0=s*16+(lane&3)*2;
        size_t o0=(size_t)qr*H_, o1=(size_t)(qr+8)*H_;
        qa_h[s][0]=*(const uint32_t*)(qhp+o0+c0);   qa_h[s][1]=*(const uint32_t*)(qhp+o1+c0);
        qa_h[s][2]=*(const uint32_t*)(qhp+o0+c0+8); qa_h[s][3]=*(const uint32_t*)(qhp+o1+c0+8);
        qa_l[s][0]=*(const uint32_t*)(qlp+o0+c0);   qa_l[s][1]=*(const uint32_t*)(qlp+o1+c0);
        qa_l[s][2]=*(const uint32_t*)(qlp+o0+c0+8); qa_l[s][3]=*(const uint32_t*)(qlp+o1+c0+8);
    }

    float o[8][4];
#pragma unroll
    for(int f=0;f<8;f++){o[f][0]=0.f;o[f][1]=0.f;o[f][2]=0.f;o[f][3]=0.f;}
    float m0=-INFINITY,m1=-INFINITY,l0=0.f,l1=0.f;
    const int rb=(lane>>4)*8+(lane&7), cb=((lane>>3)&1)*8;

    for(int j=j0;j<j1;j++){
        const int cur=(j-j0)&1;
        if(j+1<j1){
            const int nx=cur^1;
#pragma unroll
            for(int i=0;i<4;i++){
                int rr=lr+i*16;
                cpa16(su32(ksh+nx*STG+rr*KS+lc), khp+(size_t)((j+1)*64+rr)*H_+lc);
                cpa16(su32(ksl+nx*STG+rr*KS+lc), klp+(size_t)((j+1)*64+rr)*H_+lc);
                cpa16(su32(vsh+nx*STG+rr*KS+lc), vhp+(size_t)rr*T_+(j+1)*64+lc);
                cpa16(su32(vsl+nx*STG+rr*KS+lc), vlp+(size_t)rr*T_+(j+1)*64+lc);
            }
            cpcommit(); cpwait<1>();
        } else cpwait<0>();
        __syncthreads();

        float sa[8][4];
#pragma unroll
        for(int f=0;f<8;f++){sa[f][0]=0.f;sa[f][1]=0.f;sa[f][2]=0.f;sa[f][3]=0.f;}
#pragma unroll
        for(int s=0;s<4;s++)
#pragma unroll
            for(int p=0;p<4;p++){
                uint32_t bh[4],bl[4];
                ldsm4(su32(ksh+cur*STG+(p*16+rb)*KS+s*16+cb),bh[0],bh[1],bh[2],bh[3]);
                ldsm4(su32(ksl+cur*STG+(p*16+rb)*KS+s*16+cb),bl[0],bl[1],bl[2],bl[3]);
                mma16816(sa[p*2],  qa_h[s],bh[0],bh[1]);
                mma16816(sa[p*2],  qa_h[s],bl[0],bl[1]);
                mma16816(sa[p*2],  qa_l[s],bh[0],bh[1]);
                mma16816(sa[p*2+1],qa_h[s],bh[2],bh[3]);
                mma16816(sa[p*2+1],qa_h[s],bl[2],bl[3]);
                mma16816(sa[p*2+1],qa_l[s],bh[2],bh[3]);
            }

        if(j==qi){
#pragma unroll
            for(int f=0;f<8;f++){
                int kg=j*64+f*8+(lane&3)*2;
                if(kg  >qr)   sa[f][0]=-INFINITY;
                if(kg+1>qr)   sa[f][1]=-INFINITY;
                if(kg  >qr+8) sa[f][2]=-INFINITY;
                if(kg+1>qr+8) sa[f][3]=-INFINITY;
            }
        }

        float mt0=-INFINITY,mt1=-INFINITY;
#pragma unroll
        for(int f=0;f<8;f++){
            mt0=fmaxf(mt0,fmaxf(sa[f][0],sa[f][1]));
            mt1=fmaxf(mt1,fmaxf(sa[f][2],sa[f][3]));
        }
        mt0=fmaxf(mt0,__shfl_xor_sync(~0u,mt0,1)); mt0=fmaxf(mt0,__shfl_xor_sync(~0u,mt0,2));
        mt1=fmaxf(mt1,__shfl_xor_sync(~0u,mt1,1)); mt1=fmaxf(mt1,__shfl_xor_sync(~0u,mt1,2));
        float mn0=fmaxf(m0,mt0), mn1=fmaxf(m1,mt1);
        float a0=__expf(m0-mn0), a1=__expf(m1-mn1);
        float s0=0.f,s1=0.f;
#pragma unroll
        for(int f=0;f<8;f++){
            sa[f][0]=__expf(sa[f][0]-mn0); s0+=sa[f][0];
            sa[f][1]=__expf(sa[f][1]-mn0); s0+=sa[f][1];
            sa[f][2]=__expf(sa[f][2]-mn1); s1+=sa[f][2];
            sa[f][3]=__expf(sa[f][3]-mn1); s1+=sa[f][3];
        }
        s0+=__shfl_xor_sync(~0u,s0,1); s0+=__shfl_xor_sync(~0u,s0,2);
        s1+=__shfl_xor_sync(~0u,s1,1); s1+=__shfl_xor_sync(~0u,s1,2);
        l0=l0*a0+s0; l1=l1*a1+s1; m0=mn0; m1=mn1;

        uint32_t ph[4][4], pl[4][4];
#pragma unroll
        for(int s=0;s<4;s++){
            splitp(sa[2*s][0],  sa[2*s][1],  ph[s][0],pl[s][0]);
            splitp(sa[2*s][2],  sa[2*s][3],  ph[s][1],pl[s][1]);
            splitp(sa[2*s+1][0],sa[2*s+1][1],ph[s][2],pl[s][2]);
            splitp(sa[2*s+1][2],sa[2*s+1][3],ph[s][3],pl[s][3]);
        }
#pragma unroll
        for(int f=0;f<8;f++){o[f][0]*=a0;o[f][1]*=a0;o[f][2]*=a1;o[f][3]*=a1;}
#pragma unroll
        for(int s=0;s<4;s++)
#pragma unroll
            for(int p=0;p<4;p++){
                uint32_t bh[4],bl[4];
                ldsm4(su32(vsh+cur*STG+(p*16+rb)*KS+s*16+cb),bh[0],bh[1],bh[2],bh[3]);
                ldsm4(su32(vsl+cur*STG+(p*16+rb)*KS+s*16+cb),bl[0],bl[1],bl[2],bl[3]);
                mma16816(o[p*2],  ph[s],bh[0],bh[1]);
                mma16816(o[p*2],  ph[s],bl[0],bl[1]);
                mma16816(o[p*2],  pl[s],bh[0],bh[1]);
                mma16816(o[p*2+1],ph[s],bh[2],bh[3]);
                mma16816(o[p*2+1],ph[s],bl[2],bl[3]);
                mma16816(o[p*2+1],pl[s],bh[2],bh[3]);
            }
        __syncthreads();
    }

    float* pp=g_pacc+(size_t)id*4096;
#pragma unroll
    for(int f=0;f<8;f++){
        int h=f*8+(lane&3)*2;
        *(float2*)(pp+qrl*64+h)    =make_float2(o[f][0],o[f][1]);
        *(float2*)(pp+(qrl+8)*64+h)=make_float2(o[f][2],o[f][3]);
    }
    if((lane&3)==0){
        g_pm[id*64+qrl]=m0;   g_pl[id*64+qrl]=l0;
        g_pm[id*64+qrl+8]=m1; g_pl[id*64+qrl+8]=l1;
    }
}

// ------------- Kernel 3: combine split-key partials -------------------------
__global__ void __launch_bounds__(512)
comb_kernel(float* __restrict__ out){
    const int qi=blockIdx.x, b=blockIdx.y;
    const int a=qi>>3, rr=qi&7;
    const int base=b*IPB+(a+1)*(4*a+rr), nseg=a+1;
    const int ql=threadIdx.x>>3, hg=(threadIdx.x&7)*8;

    float mstar=-INFINITY;
    for(int s=0;s<nseg;s++) mstar=fmaxf(mstar,g_pm[(base+s)*64+ql]);
    float lsum=0.f, acc[8];
#pragma unroll
    for(int i=0;i<8;i++) acc[i]=0.f;
    for(int s=0;s<nseg;s++){
        float wgt=__expf(g_pm[(base+s)*64+ql]-mstar);
        lsum+=g_pl[(base+s)*64+ql]*wgt;
        const float4* p=(const float4*)(g_pacc+((size_t)(base+s)*4096+ql*64+hg));
#pragma unroll
        for(int i=0;i<2;i++){
            float4 v=p[i];
            acc[4*i]  +=wgt*v.x; acc[4*i+1]+=wgt*v.y;
            acc[4*i+2]+=wgt*v.z; acc[4*i+3]+=wgt*v.w;
        }
    }
    float inv=1.f/lsum;
    float4* po=(float4*)(out+((size_t)b*T_+qi*64+ql)*H_+hg);
#pragma unroll
    for(int i=0;i<2;i++)
        po[i]=make_float4(acc[4*i]*inv,acc[4*i+1]*inv,acc[4*i+2]*inv,acc[4*i+3]*inv);
}

extern "C" void kernel_launch(void* const* d_in, const int* in_sizes, int n_in,
                              void* d_out, int out_size){
    cudaFuncSetAttribute(qkv_kernel,  cudaFuncAttributeMaxDynamicSharedMemorySize, QKV_SMEM);
    cudaFuncSetAttribute(attn_kernel, cudaFuncAttributeMaxDynamicSharedMemorySize, ATTN_SMEM);
    prep_w<<<dim3(16,3),256>>>((const float*)d_in[1],(const float*)d_in[2],(const float*)d_in[3]);
    qkv_kernel<<<(B_*T_)/64,256,QKV_SMEM>>>((const float*)d_in[0]);
    attn_kernel<<<NIT,128,ATTN_SMEM>>>();
    comb_kernel<<<dim3(T_/64,B_),512>>>((float*)d_out);
}

// round 7
// speedup vs baseline: 7.1742x; 2.0420x over previous
#include <cuda_runtime.h>
#include <cuda_fp16.h>
#include <math.h>
#include <stdint.h>

#define B_ 4
#define T_ 4096
#define C_ 1024
#define H_ 64
#define IPB 288
#define NIT (B_*IPB)

__device__ __half g_q[B_*T_*H_];          // [b][t][h], scale 1/32 folded
__device__ __half g_k[B_*T_*H_];
__device__ __half g_v[B_*H_*T_];          // transposed [b][h][t]
__device__ __half g_w[192*C_];            // W^T [n][k]
__device__ float g_pacc[(size_t)NIT*64*64];
__device__ float g_pm[NIT*64], g_pl[NIT*64];

__device__ __forceinline__ uint32_t su32(const void* p){ return (uint32_t)__cvta_generic_to_shared(p); }
__device__ __forceinline__ void ldsm4(uint32_t a, uint32_t& r0, uint32_t& r1, uint32_t& r2, uint32_t& r3){
    asm volatile("ldmatrix.sync.aligned.m8n8.x4.shared.b16 {%0,%1,%2,%3}, [%4];"
                 : "=r"(r0),"=r"(r1),"=r"(r2),"=r"(r3) : "r"(a));
}
__device__ __forceinline__ void mmaf16(float* d, const uint32_t* a, uint32_t b0, uint32_t b1){
    asm volatile("mma.sync.aligned.m16n8k16.row.col.f32.f16.f16.f32 "
                 "{%0,%1,%2,%3}, {%4,%5,%6,%7}, {%8,%9}, {%0,%1,%2,%3};"
                 : "+f"(d[0]),"+f"(d[1]),"+f"(d[2]),"+f"(d[3])
                 : "r"(a[0]),"r"(a[1]),"r"(a[2]),"r"(a[3]),"r"(b0),"r"(b1));
}
__device__ __forceinline__ uint32_t packh2(float x, float y){
    __half2 h = __float22half2_rn(make_float2(x,y));
    return *(uint32_t*)&h;
}
__device__ __forceinline__ void cpa16(uint32_t dst, const void* src){
    asm volatile("cp.async.cg.shared.global [%0], [%1], 16;"::"r"(dst),"l"(src));
}
__device__ __forceinline__ void cpcommit(){ asm volatile("cp.async.commit_group;"); }
template<int N> __device__ __forceinline__ void cpwait(){
    asm volatile("cp.async.wait_group %0;"::"n"(N));
}

// ------------- Kernel 0: transpose weights -> fp16, fold 1/32 into Wq -------
__global__ void __launch_bounds__(256)
prep_w(const float* __restrict__ Wq, const float* __restrict__ Wk,
       const float* __restrict__ Wv){
    __shared__ float t[64][65];
    const int tid=threadIdx.x, k0=blockIdx.x*64, mat=blockIdx.y;
    const float* src = mat==0?Wq:(mat==1?Wk:Wv);
    const float sc = mat==0?0.03125f:1.f;
#pragma unroll
    for(int i=0;i<4;i++){
        int idx=tid+i*256, r=idx>>4, c=(idx&15)<<2;
        float4 v=*(const float4*)(src+(size_t)(k0+r)*H_+c);
        t[r][c]=v.x*sc; t[r][c+1]=v.y*sc; t[r][c+2]=v.z*sc; t[r][c+3]=v.w*sc;
    }
    __syncthreads();
    const int h=tid>>2, kk=(tid&3)<<4, n=mat*64+h;
#pragma unroll
    for(int m=0;m<16;m++)
        g_w[(size_t)n*C_+k0+kk+m]=__float2half(t[kk+m][h]);
}

// ------------- Kernel 1: fp16 tensor-core fused QKV, double-buffered --------
#define XS 40
#define XTS (64*XS)
#define WTS (192*XS)
__global__ void __launch_bounds__(256)
qkv_kernel(const float* __restrict__ x){
    __shared__ __half xs[2][XTS], ws[2][WTS];
    const int tid=threadIdx.x, lane=tid&31, w=tid>>5;
    const int wm=w>>2, wn=w&3;
    const int row0=blockIdx.x*64;

    float acc[2][6][4];
#pragma unroll
    for(int a=0;a<2;a++)
#pragma unroll
        for(int b=0;b<6;b++)
#pragma unroll
            for(int i=0;i<4;i++) acc[a][b][i]=0.f;

    const int ra_=(lane&15), ca_=(lane>>4)*8;
    const int rb_=(lane>>4)*8+(lane&7), cb_=((lane>>3)&1)*8;
    const int xr0=tid>>3, xc0=(tid&7)<<2;
    const int wr0=tid>>2, wc0=(tid&3)<<3;

    float4 xv[2];
    xv[0]=*(const float4*)(x+(size_t)(row0+xr0)*C_+xc0);
    xv[1]=*(const float4*)(x+(size_t)(row0+xr0+32)*C_+xc0);
#pragma unroll
    for(int i=0;i<3;i++){
        int r=wr0+i*64;
        cpa16(su32(&ws[0][r*XS+wc0]), g_w+(size_t)r*C_+wc0);
    }
    cpcommit();

    for(int k0=0, it=0; k0<C_; k0+=32, it++){
        const int cur=it&1;
        const bool more=(k0+32<C_);
        if(more){
#pragma unroll
            for(int i=0;i<3;i++){
                int r=wr0+i*64;
                cpa16(su32(&ws[cur^1][r*XS+wc0]), g_w+(size_t)r*C_+k0+32+wc0);
            }
            cpcommit();
        }
#pragma unroll
        for(int i=0;i<2;i++){
            int r=xr0+i*32;
            *(uint2*)&xs[cur][r*XS+xc0]=make_uint2(packh2(xv[i].x,xv[i].y),
                                                   packh2(xv[i].z,xv[i].w));
        }
        if(more){
            xv[0]=*(const float4*)(x+(size_t)(row0+xr0)*C_+k0+32+xc0);
            xv[1]=*(const float4*)(x+(size_t)(row0+xr0+32)*C_+k0+32+xc0);
        }
        if(more) cpwait<1>(); else cpwait<0>();
        __syncthreads();

#pragma unroll
        for(int ks=0;ks<32;ks+=16){
            uint32_t a[2][4];
#pragma unroll
            for(int mf=0;mf<2;mf++){
                int rr=wm*32+mf*16+ra_, cc=ks+ca_;
                ldsm4(su32(&xs[cur][rr*XS+cc]),a[mf][0],a[mf][1],a[mf][2],a[mf][3]);
            }
#pragma unroll
            for(int p=0;p<3;p++){
                int rr=wn*48+p*16+rb_, cc=ks+cb_;
                uint32_t b[4];
                ldsm4(su32(&ws[cur][rr*XS+cc]),b[0],b[1],b[2],b[3]);
#pragma unroll
                for(int mf=0;mf<2;mf++){
                    mmaf16(acc[mf][p*2],  a[mf],b[0],b[1]);
                    mmaf16(acc[mf][p*2+1],a[mf],b[2],b[3]);
                }
            }
        }
        __syncthreads();
    }
#pragma unroll
    for(int mf=0;mf<2;mf++){
        int r0=row0+wm*32+mf*16+(lane>>2), r1=r0+8;
#pragma unroll
        for(int nf=0;nf<6;nf++){
            int n=wn*48+nf*8+(lane&3)*2, mat=n>>6, h=n&63;
            float* d=acc[mf][nf];
            if(mat<2){
                __half* dst = mat? g_k : g_q;
                *(uint32_t*)(dst+(size_t)r0*H_+h)=packh2(d[0],d[1]);
                *(uint32_t*)(dst+(size_t)r1*H_+h)=packh2(d[2],d[3]);
            } else {
                int b0=r0>>12, t0=r0&4095, b1=r1>>12, t1=r1&4095;
                size_t o0=((size_t)b0*H_+h)*T_+t0, o1=((size_t)b1*H_+h)*T_+t1;
                g_v[o0]=__float2half(d[0]); g_v[o0+T_]=__float2half(d[1]);
                g_v[o1]=__float2half(d[2]); g_v[o1+T_]=__float2half(d[3]);
            }
        }
    }
}

// ------------- Kernel 2: fp16 split-key flash attention ---------------------
#define KS 72
#define STG (64*KS)
__global__ void __launch_bounds__(128)
attn_kernel(){
    __shared__ __half ks[2][STG], vs[2][STG];
    const int tid=threadIdx.x, lane=tid&31, w=tid>>5;
    int id=(int)gridDim.x-1-blockIdx.x;
    int b=id/IPB, r=id%IPB, qi=0;
    for(;;){ int c=(qi>>3)+1; if(r<c) break; r-=c; qi++; }
    const int j0=r*8, j1=min(j0+8, qi+1);
    const int qrl=w*16+(lane>>2), qr=qi*64+qrl;

    const __half *qp=g_q+(size_t)b*T_*H_;
    const __half *kp=g_k+(size_t)b*T_*H_;
    const __half *vp=g_v+(size_t)b*H_*T_;
    const int lr=tid>>3, lc=(tid&7)<<3;

#pragma unroll
    for(int i=0;i<4;i++){
        int rr=lr+i*16;
        cpa16(su32(&ks[0][rr*KS+lc]), kp+(size_t)(j0*64+rr)*H_+lc);
        cpa16(su32(&vs[0][rr*KS+lc]), vp+(size_t)rr*T_+j0*64+lc);
    }
    cpcommit();

    uint32_t qa[4][4];
#pragma unroll
    for(int s=0;s<4;s++){
        int c0=s*16+(lane&3)*2;
        size_t o0=(size_t)qr*H_, o1=(size_t)(qr+8)*H_;
        qa[s][0]=*(const uint32_t*)(qp+o0+c0);   qa[s][1]=*(const uint32_t*)(qp+o1+c0);
        qa[s][2]=*(const uint32_t*)(qp+o0+c0+8); qa[s][3]=*(const uint32_t*)(qp+o1+c0+8);
    }

    float o[8][4];
#pragma unroll
    for(int f=0;f<8;f++){o[f][0]=0.f;o[f][1]=0.f;o[f][2]=0.f;o[f][3]=0.f;}
    float m0=-INFINITY,m1=-INFINITY,l0=0.f,l1=0.f;
    const int rb=(lane>>4)*8+(lane&7), cb=((lane>>3)&1)*8;

    for(int j=j0;j<j1;j++){
        const int cur=(j-j0)&1;
        if(j+1<j1){
            const int nx=cur^1;
#pragma unroll
            for(int i=0;i<4;i++){
                int rr=lr+i*16;
                cpa16(su32(&ks[nx][rr*KS+lc]), kp+(size_t)((j+1)*64+rr)*H_+lc);
                cpa16(su32(&vs[nx][rr*KS+lc]), vp+(size_t)rr*T_+(j+1)*64+lc);
            }
            cpcommit(); cpwait<1>();
        } else cpwait<0>();
        __syncthreads();

        float sa[8][4];
#pragma unroll
        for(int f=0;f<8;f++){sa[f][0]=0.f;sa[f][1]=0.f;sa[f][2]=0.f;sa[f][3]=0.f;}
#pragma unroll
        for(int s=0;s<4;s++)
#pragma unroll
            for(int p=0;p<4;p++){
                uint32_t bb[4];
                ldsm4(su32(&ks[cur][(p*16+rb)*KS+s*16+cb]),bb[0],bb[1],bb[2],bb[3]);
                mmaf16(sa[p*2],  qa[s],bb[0],bb[1]);
                mmaf16(sa[p*2+1],qa[s],bb[2],bb[3]);
            }

        if(j==qi){
#pragma unroll
            for(int f=0;f<8;f++){
                int kg=j*64+f*8+(lane&3)*2;
                if(kg  >qr)   sa[f][0]=-INFINITY;
                if(kg+1>qr)   sa[f][1]=-INFINITY;
                if(kg  >qr+8) sa[f][2]=-INFINITY;
                if(kg+1>qr+8) sa[f][3]=-INFINITY;
            }
        }

        float mt0=-INFINITY,mt1=-INFINITY;
#pragma unroll
        for(int f=0;f<8;f++){
            mt0=fmaxf(mt0,fmaxf(sa[f][0],sa[f][1]));
            mt1=fmaxf(mt1,fmaxf(sa[f][2],sa[f][3]));
        }
        mt0=fmaxf(mt0,__shfl_xor_sync(~0u,mt0,1)); mt0=fmaxf(mt0,__shfl_xor_sync(~0u,mt0,2));
        mt1=fmaxf(mt1,__shfl_xor_sync(~0u,mt1,1)); mt1=fmaxf(mt1,__shfl_xor_sync(~0u,mt1,2));
        float mn0=fmaxf(m0,mt0), mn1=fmaxf(m1,mt1);
        float a0=__expf(m0-mn0), a1=__expf(m1-mn1);
        float s0=0.f,s1=0.f;
#pragma unroll
        for(int f=0;f<8;f++){
            sa[f][0]=__expf(sa[f][0]-mn0); s0+=sa[f][0];
            sa[f][1]=__expf(sa[f][1]-mn0); s0+=sa[f][1];
            sa[f][2]=__expf(sa[f][2]-mn1); s1+=sa[f][2];
            sa[f][3]=__expf(sa[f][3]-mn1); s1+=sa[f][3];
        }
        s0+=__shfl_xor_sync(~0u,s0,1); s0+=__shfl_xor_sync(~0u,s0,2);
        s1+=__shfl_xor_sync(~0u,s1,1); s1+=__shfl_xor_sync(~0u,s1,2);
        l0=l0*a0+s0; l1=l1*a1+s1; m0=mn0; m1=mn1;

        uint32_t ph[4][4];
#pragma unroll
        for(int s=0;s<4;s++){
            ph[s][0]=packh2(sa[2*s][0],  sa[2*s][1]);
            ph[s][1]=packh2(sa[2*s][2],  sa[2*s][3]);
            ph[s][2]=packh2(sa[2*s+1][0],sa[2*s+1][1]);
            ph[s][3]=packh2(sa[2*s+1][2],sa[2*s+1][3]);
        }
#pragma unroll
        for(int f=0;f<8;f++){o[f][0]*=a0;o[f][1]*=a0;o[f][2]*=a1;o[f][3]*=a1;}
#pragma unroll
        for(int s=0;s<4;s++)
#pragma unroll
            for(int p=0;p<4;p++){
                uint32_t bb[4];
                ldsm4(su32(&vs[cur][(p*16+rb)*KS+s*16+cb]),bb[0],bb[1],bb[2],bb[3]);
                mmaf16(o[p*2],  ph[s],bb[0],bb[1]);
                mmaf16(o[p*2+1],ph[s],bb[2],bb[3]);
            }
        __syncthreads();
    }

    float* pp=g_pacc+(size_t)id*4096;
#pragma unroll
    for(int f=0;f<8;f++){
        int h=f*8+(lane&3)*2;
        *(float2*)(pp+qrl*64+h)    =make_float2(o[f][0],o[f][1]);
        *(float2*)(pp+(qrl+8)*64+h)=make_float2(o[f][2],o[f][3]);
    }
    if((lane&3)==0){
        g_pm[id*64+qrl]=m0;   g_pl[id*64+qrl]=l0;
        g_pm[id*64+qrl+8]=m1; g_pl[id*64+qrl+8]=l1;
    }
}

// ------------- Kernel 3: combine split-key partials -------------------------
__global__ void __launch_bounds__(512)
comb_kernel(float* __restrict__ out){
    const int qi=blockIdx.x, b=blockIdx.y;
    const int a=qi>>3, rr=qi&7;
    const int base=b*IPB+(a+1)*(4*a+rr), nseg=a+1;
    const int ql=threadIdx.x>>3, hg=(threadIdx.x&7)*8;

    float mstar=-INFINITY;
    for(int s=0;s<nseg;s++) mstar=fmaxf(mstar,g_pm[(base+s)*64+ql]);
    float lsum=0.f, acc[8];
#pragma unroll
    for(int i=0;i<8;i++) acc[i]=0.f;
    for(int s=0;s<nseg;s++){
        float wgt=__expf(g_pm[(base+s)*64+ql]-mstar);
        lsum+=g_pl[(base+s)*64+ql]*wgt;
        const float4* p=(const float4*)(g_pacc+((size_t)(base+s)*4096+ql*64+hg));
#pragma unroll
        for(int i=0;i<2;i++){
            float4 v=p[i];
            acc[4*i]  +=wgt*v.x; acc[4*i+1]+=wgt*v.y;
            acc[4*i+2]+=wgt*v.z; acc[4*i+3]+=wgt*v.w;
        }
    }
    float inv=1.f/lsum;
    float4* po=(float4*)(out+((size_t)b*T_+qi*64+ql)*H_+hg);
#pragma unroll
    for(int i=0;i<2;i++)
        po[i]=make_float4(acc[4*i]*inv,acc[4*i+1]*inv,acc[4*i+2]*inv,acc[4*i+3]*inv);
}

extern "C" void kernel_launch(void* const* d_in, const int* in_sizes, int n_in,
                              void* d_out, int out_size){
    prep_w<<<dim3(16,3),256>>>((const float*)d_in[1],(const float*)d_in[2],(const float*)d_in[3]);
    qkv_kernel<<<(B_*T_)/64,256>>>((const float*)d_in[0]);
    attn_kernel<<<NIT,128>>>();
    comb_kernel<<<dim3(T_/64,B_),512>>>((float*)d_out);
}

// round 8
// speedup vs baseline: 7.2125x; 1.0053x over previous
#include <cuda_runtime.h>
#include <cuda_fp16.h>
#include <math.h>
#include <stdint.h>

#define B_ 4
#define T_ 4096
#define C_ 1024
#define H_ 64
#define IPB 80                       // per-batch items: sum over 32 qtiles of (qq/8+1)
#define NIT (B_*IPB)                 // 320

__device__ __half g_q[B_*T_*H_];     // [b][t][h], 1/32 folded
__device__ __half g_k[B_*T_*H_];
__device__ __half g_v[B_*H_*T_];     // transposed [b][h][t]
__device__ __half g_w[192*C_];       // W^T [n][k]
__device__ float g_pacc[(size_t)NIT*128*64];
__device__ float g_pm[NIT*128], g_pl[NIT*128];

__device__ __forceinline__ uint32_t su32(const void* p){ return (uint32_t)__cvta_generic_to_shared(p); }
__device__ __forceinline__ void ldsm4(uint32_t a, uint32_t& r0, uint32_t& r1, uint32_t& r2, uint32_t& r3){
    asm volatile("ldmatrix.sync.aligned.m8n8.x4.shared.b16 {%0,%1,%2,%3}, [%4];"
                 : "=r"(r0),"=r"(r1),"=r"(r2),"=r"(r3) : "r"(a));
}
__device__ __forceinline__ void mmaf16(float* d, const uint32_t* a, uint32_t b0, uint32_t b1){
    asm volatile("mma.sync.aligned.m16n8k16.row.col.f32.f16.f16.f32 "
                 "{%0,%1,%2,%3}, {%4,%5,%6,%7}, {%8,%9}, {%0,%1,%2,%3};"
                 : "+f"(d[0]),"+f"(d[1]),"+f"(d[2]),"+f"(d[3])
                 : "r"(a[0]),"r"(a[1]),"r"(a[2]),"r"(a[3]),"r"(b0),"r"(b1));
}
__device__ __forceinline__ uint32_t packh2(float x, float y){
    __half2 h = __float22half2_rn(make_float2(x,y));
    return *(uint32_t*)&h;
}
__device__ __forceinline__ void cpa16(uint32_t dst, const void* src){
    asm volatile("cp.async.cg.shared.global [%0], [%1], 16;"::"r"(dst),"l"(src));
}
__device__ __forceinline__ void cpcommit(){ asm volatile("cp.async.commit_group;"); }
template<int N> __device__ __forceinline__ void cpwait(){
    asm volatile("cp.async.wait_group %0;"::"n"(N));
}

// ------------- Kernel 0: transpose weights -> fp16, fold 1/32 into Wq -------
__global__ void __launch_bounds__(256)
prep_w(const float* __restrict__ Wq, const float* __restrict__ Wk,
       const float* __restrict__ Wv){
    __shared__ float t[64][65];
    const int tid=threadIdx.x, k0=blockIdx.x*64, mat=blockIdx.y;
    const float* src = mat==0?Wq:(mat==1?Wk:Wv);
    const float sc = mat==0?0.03125f:1.f;
#pragma unroll
    for(int i=0;i<4;i++){
        int idx=tid+i*256, r=idx>>4, c=(idx&15)<<2;
        float4 v=*(const float4*)(src+(size_t)(k0+r)*H_+c);
        t[r][c]=v.x*sc; t[r][c+1]=v.y*sc; t[r][c+2]=v.z*sc; t[r][c+3]=v.w*sc;
    }
    __syncthreads();
    const int h=tid>>2, kk=(tid&3)<<4, n=mat*64+h;
#pragma unroll
    for(int m=0;m<16;m++)
        g_w[(size_t)n*C_+k0+kk+m]=__float2half(t[kk+m][h]);
}

// ------------- Kernel 1: fp16 tensor-core fused QKV (unchanged R7) ----------
#define XS 40
#define XTS (64*XS)
#define WTS (192*XS)
__global__ void __launch_bounds__(256)
qkv_kernel(const float* __restrict__ x){
    __shared__ __half xs[2][XTS], ws[2][WTS];
    const int tid=threadIdx.x, lane=tid&31, w=tid>>5;
    const int wm=w>>2, wn=w&3;
    const int row0=blockIdx.x*64;

    float acc[2][6][4];
#pragma unroll
    for(int a=0;a<2;a++)
#pragma unroll
        for(int b=0;b<6;b++)
#pragma unroll
            for(int i=0;i<4;i++) acc[a][b][i]=0.f;

    const int ra_=(lane&15), ca_=(lane>>4)*8;
    const int rb_=(lane>>4)*8+(lane&7), cb_=((lane>>3)&1)*8;
    const int xr0=tid>>3, xc0=(tid&7)<<2;
    const int wr0=tid>>2, wc0=(tid&3)<<3;

    float4 xv[2];
    xv[0]=*(const float4*)(x+(size_t)(row0+xr0)*C_+xc0);
    xv[1]=*(const float4*)(x+(size_t)(row0+xr0+32)*C_+xc0);
#pragma unroll
    for(int i=0;i<3;i++){
        int r=wr0+i*64;
        cpa16(su32(&ws[0][r*XS+wc0]), g_w+(size_t)r*C_+wc0);
    }
    cpcommit();

    for(int k0=0, it=0; k0<C_; k0+=32, it++){
        const int cur=it&1;
        const bool more=(k0+32<C_);
        if(more){
#pragma unroll
            for(int i=0;i<3;i++){
                int r=wr0+i*64;
                cpa16(su32(&ws[cur^1][r*XS+wc0]), g_w+(size_t)r*C_+k0+32+wc0);
            }
            cpcommit();
        }
#pragma unroll
        for(int i=0;i<2;i++){
            int r=xr0+i*32;
            *(uint2*)&xs[cur][r*XS+xc0]=make_uint2(packh2(xv[i].x,xv[i].y),
                                                   packh2(xv[i].z,xv[i].w));
        }
        if(more){
            xv[0]=*(const float4*)(x+(size_t)(row0+xr0)*C_+k0+32+xc0);
            xv[1]=*(const float4*)(x+(size_t)(row0+xr0+32)*C_+k0+32+xc0);
        }
        if(more) cpwait<1>(); else cpwait<0>();
        __syncthreads();

#pragma unroll
        for(int ks=0;ks<32;ks+=16){
            uint32_t a[2][4];
#pragma unroll
            for(int mf=0;mf<2;mf++){
                int rr=wm*32+mf*16+ra_, cc=ks+ca_;
                ldsm4(su32(&xs[cur][rr*XS+cc]),a[mf][0],a[mf][1],a[mf][2],a[mf][3]);
            }
#pragma unroll
            for(int p=0;p<3;p++){
                int rr=wn*48+p*16+rb_, cc=ks+cb_;
                uint32_t b[4];
                ldsm4(su32(&ws[cur][rr*XS+cc]),b[0],b[1],b[2],b[3]);
#pragma unroll
                for(int mf=0;mf<2;mf++){
                    mmaf16(acc[mf][p*2],  a[mf],b[0],b[1]);
                    mmaf16(acc[mf][p*2+1],a[mf],b[2],b[3]);
                }
            }
        }
        __syncthreads();
    }
#pragma unroll
    for(int mf=0;mf<2;mf++){
        int r0=row0+wm*32+mf*16+(lane>>2), r1=r0+8;
#pragma unroll
        for(int nf=0;nf<6;nf++){
            int n=wn*48+nf*8+(lane&3)*2, mat=n>>6, h=n&63;
            float* d=acc[mf][nf];
            if(mat<2){
                __half* dst = mat? g_k : g_q;
                *(uint32_t*)(dst+(size_t)r0*H_+h)=packh2(d[0],d[1]);
                *(uint32_t*)(dst+(size_t)r1*H_+h)=packh2(d[2],d[3]);
            } else {
                int b0=r0>>12, t0=r0&4095, b1=r1>>12, t1=r1&4095;
                size_t o0=((size_t)b0*H_+h)*T_+t0, o1=((size_t)b1*H_+h)*T_+t1;
                g_v[o0]=__float2half(d[0]); g_v[o0+T_]=__float2half(d[1]);
                g_v[o1]=__float2half(d[2]); g_v[o1+T_]=__float2half(d[3]);
            }
        }
    }
}

// ------------- Kernel 2: fp16 flash attention, 128q CTA, m32 warps ----------
// CTA=(b,qq,seg): 128 queries, seg of <=16 key-tiles (64 keys each).
#define KS 72
#define STG (64*KS)
__global__ void __launch_bounds__(128)
attn_kernel(float* __restrict__ out){
    __shared__ __half ks[2][STG], vs[2][STG];
    const int tid=threadIdx.x, lane=tid&31, w=tid>>5;
    int id=(int)gridDim.x-1-blockIdx.x;              // heavy first
    int b=id/IPB, r=id%IPB, qq=0;
    for(;;){ int c=(qq>>3)+1; if(r<c) break; r-=c; qq++; }
    const int seg=r, nsegs=(qq>>3)+1;
    const int j0=seg*16, j1=min(j0+16, 2*qq+2);
    const int qrb=qq*128 + w*32 + (lane>>2);          // mf rows: qrb+mf*16, +8

    const __half *qp=g_q+(size_t)b*T_*H_;
    const __half *kp=g_k+(size_t)b*T_*H_;
    const __half *vp=g_v+(size_t)b*H_*T_;
    const int lr=tid>>3, lc=(tid&7)<<3;

#pragma unroll
    for(int i=0;i<4;i++){
        int rr=lr+i*16;
        cpa16(su32(&ks[0][rr*KS+lc]), kp+(size_t)(j0*64+rr)*H_+lc);
        cpa16(su32(&vs[0][rr*KS+lc]), vp+(size_t)rr*T_+j0*64+lc);
    }
    cpcommit();

    uint32_t qa[2][4][4];
#pragma unroll
    for(int mf=0;mf<2;mf++)
#pragma unroll
        for(int s=0;s<4;s++){
            int c0=s*16+(lane&3)*2;
            size_t o0=(size_t)(qrb+mf*16)*H_, o1=(size_t)(qrb+mf*16+8)*H_;
            qa[mf][s][0]=*(const uint32_t*)(qp+o0+c0);
            qa[mf][s][1]=*(const uint32_t*)(qp+o1+c0);
            qa[mf][s][2]=*(const uint32_t*)(qp+o0+c0+8);
            qa[mf][s][3]=*(const uint32_t*)(qp+o1+c0+8);
        }

    float o[2][8][4];
#pragma unroll
    for(int mf=0;mf<2;mf++)
#pragma unroll
        for(int f=0;f<8;f++){o[mf][f][0]=0.f;o[mf][f][1]=0.f;o[mf][f][2]=0.f;o[mf][f][3]=0.f;}
    float m[2][2], l[2][2];
#pragma unroll
    for(int mf=0;mf<2;mf++){m[mf][0]=-INFINITY;m[mf][1]=-INFINITY;l[mf][0]=0.f;l[mf][1]=0.f;}
    const int rb=(lane>>4)*8+(lane&7), cb=((lane>>3)&1)*8;

    for(int j=j0;j<j1;j++){
        const int cur=(j-j0)&1;
        if(j+1<j1){
            const int nx=cur^1;
#pragma unroll
            for(int i=0;i<4;i++){
                int rr=lr+i*16;
                cpa16(su32(&ks[nx][rr*KS+lc]), kp+(size_t)((j+1)*64+rr)*H_+lc);
                cpa16(su32(&vs[nx][rr*KS+lc]), vp+(size_t)rr*T_+(j+1)*64+lc);
            }
            cpcommit(); cpwait<1>();
        } else cpwait<0>();
        __syncthreads();

        // ---- S = Q K^T ----
        float sa[2][8][4];
#pragma unroll
        for(int mf=0;mf<2;mf++)
#pragma unroll
            for(int f=0;f<8;f++){sa[mf][f][0]=0.f;sa[mf][f][1]=0.f;sa[mf][f][2]=0.f;sa[mf][f][3]=0.f;}
#pragma unroll
        for(int s=0;s<4;s++)
#pragma unroll
            for(int p=0;p<4;p++){
                uint32_t bb[4];
                ldsm4(su32(&ks[cur][(p*16+rb)*KS+s*16+cb]),bb[0],bb[1],bb[2],bb[3]);
#pragma unroll
                for(int mf=0;mf<2;mf++){
                    mmaf16(sa[mf][p*2],  qa[mf][s],bb[0],bb[1]);
                    mmaf16(sa[mf][p*2+1],qa[mf][s],bb[2],bb[3]);
                }
            }

        // ---- causal mask (last two key tiles only) ----
        if(j>=2*qq){
#pragma unroll
            for(int mf=0;mf<2;mf++){
                int q0=qrb+mf*16, q1=q0+8;
#pragma unroll
                for(int f=0;f<8;f++){
                    int kg=j*64+f*8+(lane&3)*2;
                    if(kg  >q0) sa[mf][f][0]=-INFINITY;
                    if(kg+1>q0) sa[mf][f][1]=-INFINITY;
                    if(kg  >q1) sa[mf][f][2]=-INFINITY;
                    if(kg+1>q1) sa[mf][f][3]=-INFINITY;
                }
            }
        }

        // ---- online softmax + P frags + O rescale ----
        uint32_t ph[2][4][4];
#pragma unroll
        for(int mf=0;mf<2;mf++){
            float mt0=-INFINITY,mt1=-INFINITY;
#pragma unroll
            for(int f=0;f<8;f++){
                mt0=fmaxf(mt0,fmaxf(sa[mf][f][0],sa[mf][f][1]));
                mt1=fmaxf(mt1,fmaxf(sa[mf][f][2],sa[mf][f][3]));
            }
            mt0=fmaxf(mt0,__shfl_xor_sync(~0u,mt0,1)); mt0=fmaxf(mt0,__shfl_xor_sync(~0u,mt0,2));
            mt1=fmaxf(mt1,__shfl_xor_sync(~0u,mt1,1)); mt1=fmaxf(mt1,__shfl_xor_sync(~0u,mt1,2));
            float mn0=fmaxf(m[mf][0],mt0), mn1=fmaxf(m[mf][1],mt1);
            float a0=__expf(m[mf][0]-mn0), a1=__expf(m[mf][1]-mn1);
            float s0=0.f,s1=0.f;
#pragma unroll
            for(int f=0;f<8;f++){
                sa[mf][f][0]=__expf(sa[mf][f][0]-mn0); s0+=sa[mf][f][0];
                sa[mf][f][1]=__expf(sa[mf][f][1]-mn0); s0+=sa[mf][f][1];
                sa[mf][f][2]=__expf(sa[mf][f][2]-mn1); s1+=sa[mf][f][2];
                sa[mf][f][3]=__expf(sa[mf][f][3]-mn1); s1+=sa[mf][f][3];
            }
            s0+=__shfl_xor_sync(~0u,s0,1); s0+=__shfl_xor_sync(~0u,s0,2);
            s1+=__shfl_xor_sync(~0u,s1,1); s1+=__shfl_xor_sync(~0u,s1,2);
            l[mf][0]=l[mf][0]*a0+s0; l[mf][1]=l[mf][1]*a1+s1;
            m[mf][0]=mn0; m[mf][1]=mn1;
#pragma unroll
            for(int f=0;f<8;f++){
                o[mf][f][0]*=a0; o[mf][f][1]*=a0; o[mf][f][2]*=a1; o[mf][f][3]*=a1;
            }
#pragma unroll
            for(int s=0;s<4;s++){
                ph[mf][s][0]=packh2(sa[mf][2*s][0],  sa[mf][2*s][1]);
                ph[mf][s][1]=packh2(sa[mf][2*s][2],  sa[mf][2*s][3]);
                ph[mf][s][2]=packh2(sa[mf][2*s+1][0],sa[mf][2*s+1][1]);
                ph[mf][s][3]=packh2(sa[mf][2*s+1][2],sa[mf][2*s+1][3]);
            }
        }

        // ---- O += P V ----
#pragma unroll
        for(int s=0;s<4;s++)
#pragma unroll
            for(int p=0;p<4;p++){
                uint32_t bb[4];
                ldsm4(su32(&vs[cur][(p*16+rb)*KS+s*16+cb]),bb[0],bb[1],bb[2],bb[3]);
#pragma unroll
                for(int mf=0;mf<2;mf++){
                    mmaf16(o[mf][p*2],  ph[mf][s],bb[0],bb[1]);
                    mmaf16(o[mf][p*2+1],ph[mf][s],bb[2],bb[3]);
                }
            }
        __syncthreads();
    }

    if(nsegs==1){
        // single segment (qq<8): write normalized output directly
#pragma unroll
        for(int mf=0;mf<2;mf++){
            int r0=qrb+mf*16, r1=r0+8;
            float i0=1.f/l[mf][0], i1=1.f/l[mf][1];
            size_t ob0=((size_t)b*T_+r0)*H_, ob1=((size_t)b*T_+r1)*H_;
#pragma unroll
            for(int f=0;f<8;f++){
                int h=f*8+(lane&3)*2;
                *(float2*)(out+ob0+h)=make_float2(o[mf][f][0]*i0,o[mf][f][1]*i0);
                *(float2*)(out+ob1+h)=make_float2(o[mf][f][2]*i1,o[mf][f][3]*i1);
            }
        }
    } else {
        float* pp=g_pacc+(size_t)id*8192;
#pragma unroll
        for(int mf=0;mf<2;mf++){
            int rl0=w*32+mf*16+(lane>>2), rl1=rl0+8;
#pragma unroll
            for(int f=0;f<8;f++){
                int h=f*8+(lane&3)*2;
                *(float2*)(pp+rl0*64+h)=make_float2(o[mf][f][0],o[mf][f][1]);
                *(float2*)(pp+rl1*64+h)=make_float2(o[mf][f][2],o[mf][f][3]);
            }
            if((lane&3)==0){
                g_pm[id*128+rl0]=m[mf][0]; g_pl[id*128+rl0]=l[mf][0];
                g_pm[id*128+rl1]=m[mf][1]; g_pl[id*128+rl1]=l[mf][1];
            }
        }
    }
}

// ------------- Kernel 3: combine partials (qq>=8 only) ----------------------
__global__ void __launch_bounds__(512)
comb_kernel(float* __restrict__ out){
    const int qq=blockIdx.x+8, b=blockIdx.y;
    const int g=qq>>3, rr=qq&7;
    const int base=b*IPB+(g+1)*(4*g+rr), nseg=g+1;
    const int ql=threadIdx.x>>2, hg=(threadIdx.x&3)*16;

    float mstar=-INFINITY;
    for(int s=0;s<nseg;s++) mstar=fmaxf(mstar,g_pm[(base+s)*128+ql]);
    float lsum=0.f, acc[16];
#pragma unroll
    for(int i=0;i<16;i++) acc[i]=0.f;
    for(int s=0;s<nseg;s++){
        float wgt=__expf(g_pm[(base+s)*128+ql]-mstar);
        lsum+=g_pl[(base+s)*128+ql]*wgt;
        const float4* p=(const float4*)(g_pacc+((size_t)(base+s)*8192+ql*64+hg));
#pragma unroll
        for(int i=0;i<4;i++){
            float4 v=p[i];
            acc[4*i]  +=wgt*v.x; acc[4*i+1]+=wgt*v.y;
            acc[4*i+2]+=wgt*v.z; acc[4*i+3]+=wgt*v.w;
        }
    }
    float inv=1.f/lsum;
    float4* po=(float4*)(out+((size_t)b*T_+qq*128+ql)*H_+hg);
#pragma unroll
    for(int i=0;i<4;i++)
        po[i]=make_float4(acc[4*i]*inv,acc[4*i+1]*inv,acc[4*i+2]*inv,acc[4*i+3]*inv);
}

extern "C" void kernel_launch(void* const* d_in, const int* in_sizes, int n_in,
                              void* d_out, int out_size){
    prep_w<<<dim3(16,3),256>>>((const float*)d_in[1],(const float*)d_in[2],(const float*)d_in[3]);
    qkv_kernel<<<(B_*T_)/64,256>>>((const float*)d_in[0]);
    attn_kernel<<<NIT,128>>>((float*)d_out);
    comb_kernel<<<dim3(24,4),512>>>((float*)d_out);
}